// round 10
// baseline (speedup 1.0000x reference)
#include <cuda_runtime.h>
#include <cuda_fp16.h>
#include <math.h>
#include <stdint.h>

// Problem constants
static constexpr int B_ = 4, S_ = 1024, D_ = 512, H_ = 8, F_ = 2048, DH_ = 64, L_ = 8;
static constexpr int M_ROWS = B_ * S_;           // 4096
static constexpr float QK_SCALE = 0.125f;        // 1/sqrt(64)
static constexpr float LN_EPS = 1e-5f;

static constexpr long MD = (long)M_ROWS * D_;    // 2097152
// transposed half weight slabs: [N,K] row-major per layer
static constexpr long SZ_QKV = 1536L * 512, SZ_O = 512L * 512, SZ_1 = 2048L * 512, SZ_2 = 512L * 2048;
static constexpr long OFF_TQKV = 0, OFF_TO = 8 * SZ_QKV, OFF_T1 = OFF_TO + 8 * SZ_O, OFF_T2 = OFF_T1 + 8 * SZ_1;

// Scratch (device globals; no allocation anywhere)
__device__ float g_x[M_ROWS * D_];                          // exact fp32 residual stream
__device__ __align__(16) __half g_xh[M_ROWS * D_];          // half copy for GEMM A
__device__ __align__(16) __half g_qkv[3 * M_ROWS * D_];     // q,k [B,H,S,DH]; vT [B,H,DH,S]
__device__ __align__(16) __half g_attn[M_ROWS * D_];
__device__ __align__(16) __half g_ffn[M_ROWS * F_];
__device__ __align__(16) __half g_wH[8 * (SZ_QKV + SZ_O + SZ_1 + SZ_2)];   // ~50 MB

enum { M_GELU = 3, M_QKV = 6 };

// ---------------------------------------------------------------------------
// helpers
// ---------------------------------------------------------------------------
__device__ __forceinline__ void cpa16(uint32_t smem, const void* gptr) {
    asm volatile("cp.async.cg.shared.global [%0], [%1], 16;\n" :: "r"(smem), "l"(gptr));
}
__device__ __forceinline__ void cp_commit() {
    asm volatile("cp.async.commit_group;\n" ::);
}
template <int N>
__device__ __forceinline__ void cp_wait() {
    asm volatile("cp.async.wait_group %0;\n" :: "n"(N));
}
__device__ __forceinline__ uint32_t smem_u32(const void* p) {
    return (uint32_t)__cvta_generic_to_shared(p);
}

__device__ __forceinline__ void ldsm4(uint32_t& r0, uint32_t& r1, uint32_t& r2,
                                      uint32_t& r3, uint32_t addr) {
    asm volatile("ldmatrix.sync.aligned.m8n8.x4.shared.b16 {%0,%1,%2,%3}, [%4];"
                 : "=r"(r0), "=r"(r1), "=r"(r2), "=r"(r3) : "r"(addr));
}

// m16n8k16 f16 mma, fp32 accumulate
__device__ __forceinline__ void mma16(float* c, const uint32_t* a, const uint32_t* b) {
    asm("mma.sync.aligned.m16n8k16.row.col.f32.f16.f16.f32 "
        "{%0,%1,%2,%3}, {%4,%5,%6,%7}, {%8,%9}, {%0,%1,%2,%3};"
        : "+f"(c[0]), "+f"(c[1]), "+f"(c[2]), "+f"(c[3])
        : "r"(a[0]), "r"(a[1]), "r"(a[2]), "r"(a[3]), "r"(b[0]), "r"(b[1]));
}

// ---------------------------------------------------------------------------
// fp16 mma GEMM (QKV / FFN1): 128 threads, 4 warps of 64x(BN/2), BK=32,
// 3-stage cp.async. C[m,n] = A[m,k] * Bt[n,k]^T
// ---------------------------------------------------------------------------
static constexpr int G_ASTR = 40;  // halfs per row (32 + 8 pad)
template <int BM, int BN>
static constexpr int smem_bytes() { return 3 * (BM + BN) * G_ASTR * 2; }

template <int BM, int BN, int MODE>
__global__ __launch_bounds__(128)
void mma_gemm(const __half* __restrict__ A, const __half* __restrict__ Bm,
              const float* __restrict__ b0, const float* __restrict__ b1,
              const float* __restrict__ b2,
              __half* __restrict__ Ch, int N, int K)
{
    constexpr int BK = 32;
    constexpr int WM = 64, WN = BN / 2;
    constexpr int MI = WM / 16, NI = WN / 8;
    constexpr int ASZ = BM * G_ASTR;
    constexpr int BSZ = BN * G_ASTR;

    extern __shared__ __align__(16) __half smh[];
    __half* As = smh;
    __half* Bs = smh + 3 * ASZ;

    const int bm = blockIdx.y * BM;
    const int bn = blockIdx.x * BN;
    const int tid = threadIdx.x;
    const int lane = tid & 31;
    const int warp = tid >> 5;
    const int wm0 = (warp >> 1) * WM;
    const int wn0 = (warp & 1) * WN;
    const int lr = lane >> 2;
    const int lc = lane & 3;
    const int arow = lane & 15, acol = (lane >> 4) << 3;
    const int brow = ((lane >> 4) << 3) + (lane & 7);
    const int bcol = ((lane >> 3) & 1) << 3;

    float acc[MI][NI][4];
    #pragma unroll
    for (int i = 0; i < MI; i++)
        #pragma unroll
        for (int j = 0; j < NI; j++)
            #pragma unroll
            for (int q = 0; q < 4; q++) acc[i][j][q] = 0.0f;

    auto load_stage = [&](int j) {
        const int st = j % 3;
        __half* as = As + st * ASZ;
        #pragma unroll
        for (int c = tid; c < BM * 4; c += 128) {
            int r = c >> 2, q = (c & 3) * 8;
            cpa16(smem_u32(as + r * G_ASTR + q), A + (long)(bm + r) * K + j * BK + q);
        }
        __half* bs = Bs + st * BSZ;
        #pragma unroll
        for (int c = tid; c < BN * 4; c += 128) {
            int r = c >> 2, q = (c & 3) * 8;
            cpa16(smem_u32(bs + r * G_ASTR + q), Bm + (long)(bn + r) * K + j * BK + q);
        }
        cp_commit();
    };

    const int NIT = K / BK;
    load_stage(0);
    if (NIT > 1) load_stage(1);

    for (int it = 0; it < NIT; it++) {
        if (it + 2 < NIT) { load_stage(it + 2); cp_wait<2>(); }
        else if (it + 2 == NIT) { cp_wait<1>(); }
        else { cp_wait<0>(); }
        __syncthreads();

        const int st = it % 3;
        const __half* as = As + st * ASZ;
        const __half* bs = Bs + st * BSZ;
        #pragma unroll
        for (int kk = 0; kk < BK; kk += 16) {
            uint32_t af[MI][4];
            #pragma unroll
            for (int mi = 0; mi < MI; mi++)
                ldsm4(af[mi][0], af[mi][1], af[mi][2], af[mi][3],
                      smem_u32(as + (wm0 + mi * 16 + arow) * G_ASTR + kk + acol));
            uint32_t bf[NI][2];
            #pragma unroll
            for (int ni = 0; ni < NI; ni += 2)
                ldsm4(bf[ni][0], bf[ni][1], bf[ni + 1][0], bf[ni + 1][1],
                      smem_u32(bs + (wn0 + ni * 8 + brow) * G_ASTR + kk + bcol));
            #pragma unroll
            for (int mi = 0; mi < MI; mi++)
                #pragma unroll
                for (int ni = 0; ni < NI; ni++)
                    mma16(acc[mi][ni], af[mi], bf[ni]);
        }
        __syncthreads();
    }

    #pragma unroll
    for (int mi = 0; mi < MI; mi++) {
        #pragma unroll
        for (int ni = 0; ni < NI; ni++) {
            #pragma unroll
            for (int ri = 0; ri < 2; ri++) {
                const int m = bm + wm0 + mi * 16 + lr + ri * 8;
                const int n = bn + wn0 + ni * 8 + lc * 2;
                float v0 = acc[mi][ni][ri * 2 + 0];
                float v1 = acc[mi][ni][ri * 2 + 1];
                if (MODE == M_GELU) {
                    v0 += b0[n]; v1 += b0[n + 1];
                    float g0 = 0.5f * v0 * (1.0f + erff(v0 * 0.70710678118654752f));
                    float g1 = 0.5f * v1 * (1.0f + erff(v1 * 0.70710678118654752f));
                    *reinterpret_cast<__half2*>(Ch + (long)m * N + n) = __floats2half2_rn(g0, g1);
                } else { // M_QKV
                    const int t = n >> 9;
                    const int colD = n & 511;
                    const float* bb = (t == 0) ? b0 : ((t == 1) ? b1 : b2);
                    const int b = m >> 10, s = m & 1023, h = colD >> 6, dh0 = colD & 63;
                    const int bh = (b << 3) + h;
                    float u0 = v0 + bb[colD], u1 = v1 + bb[colD + 1];
                    if (t == 0) { u0 *= QK_SCALE; u1 *= QK_SCALE; }
                    if (t == 2) {
                        long o = 2 * MD + ((long)bh << 16) + ((long)dh0 << 10) + s;
                        Ch[o]        = __float2half_rn(u0);
                        Ch[o + 1024] = __float2half_rn(u1);
                    } else {
                        long o = (long)t * MD + (((long)bh * S_ + s) << 6) + dh0;
                        *reinterpret_cast<__half2*>(Ch + o) = __floats2half2_rn(u0, u1);
                    }
                }
            }
        }
    }
}

// ---------------------------------------------------------------------------
// Fused GEMM + bias + residual + LayerNorm. One CTA owns 32 full rows (N=512).
// 256 threads = 8 warps, each warp 32x64. BK=32, 2-stage cp.async.
// outF = LN(A*B^T + bias + res) fp32; outH = half copy.
// ---------------------------------------------------------------------------
static constexpr int LN_ASZ = 32 * G_ASTR;            // 1280 halfs / A stage
static constexpr int LN_BSZ = 512 * G_ASTR;           // 20480 halfs / B stage
static constexpr int LN_SMEM = 2 * (LN_ASZ + LN_BSZ) * 2;   // 87040 B

__global__ __launch_bounds__(256, 2)
void gemm_ln(const __half* __restrict__ A, const __half* __restrict__ Bm,
             const float* __restrict__ bias, const float* __restrict__ res,
             const float* __restrict__ g, const float* __restrict__ be,
             float* __restrict__ outF, __half* __restrict__ outH, int K)
{
    constexpr int BK = 32, MI = 2, NI = 8;

    extern __shared__ __align__(16) __half smh[];
    __half* As = smh;                     // 2 x LN_ASZ
    __half* Bs = smh + 2 * LN_ASZ;        // 2 x LN_BSZ
    __shared__ float sred[8][32], sqred[8][32];
    __shared__ float smean[32], sinv[32];

    const int bm = blockIdx.x * 32;
    const int tid = threadIdx.x;
    const int lane = tid & 31;
    const int warp = tid >> 5;
    const int wn0 = warp * 64;
    const int lr = lane >> 2;
    const int lc = lane & 3;
    const int arow = lane & 15, acol = (lane >> 4) << 3;
    const int brow = ((lane >> 4) << 3) + (lane & 7);
    const int bcol = ((lane >> 3) & 1) << 3;

    float acc[MI][NI][4];
    #pragma unroll
    for (int i = 0; i < MI; i++)
        #pragma unroll
        for (int j = 0; j < NI; j++)
            #pragma unroll
            for (int q = 0; q < 4; q++) acc[i][j][q] = 0.0f;

    auto load_stage = [&](int j) {
        const int st = j & 1;
        __half* as = As + st * LN_ASZ;
        #pragma unroll
        for (int c = tid; c < 32 * 4; c += 256) {
            int r = c >> 2, q = (c & 3) * 8;
            cpa16(smem_u32(as + r * G_ASTR + q), A + (long)(bm + r) * K + j * BK + q);
        }
        __half* bs = Bs + st * LN_BSZ;
        #pragma unroll
        for (int c = tid; c < 512 * 4; c += 256) {
            int r = c >> 2, q = (c & 3) * 8;
            cpa16(smem_u32(bs + r * G_ASTR + q), Bm + (long)r * K + j * BK + q);
        }
        cp_commit();
    };

    const int NIT = K / BK;
    load_stage(0);

    for (int it = 0; it < NIT; it++) {
        if (it + 1 < NIT) { load_stage(it + 1); cp_wait<1>(); }
        else              { cp_wait<0>(); }
        __syncthreads();

        const int st = it & 1;
        const __half* as = As + st * LN_ASZ;
        const __half* bs = Bs + st * LN_BSZ;
        #pragma unroll
        for (int kk = 0; kk < BK; kk += 16) {
            uint32_t af[MI][4];
            #pragma unroll
            for (int mi = 0; mi < MI; mi++)
                ldsm4(af[mi][0], af[mi][1], af[mi][2], af[mi][3],
                      smem_u32(as + (mi * 16 + arow) * G_ASTR + kk + acol));
            uint32_t bf[NI][2];
            #pragma unroll
            for (int ni = 0; ni < NI; ni += 2)
                ldsm4(bf[ni][0], bf[ni][1], bf[ni + 1][0], bf[ni + 1][1],
                      smem_u32(bs + (wn0 + ni * 8 + brow) * G_ASTR + kk + bcol));
            #pragma unroll
            for (int mi = 0; mi < MI; mi++)
                #pragma unroll
                for (int ni = 0; ni < NI; ni++)
                    mma16(acc[mi][ni], af[mi], bf[ni]);
        }
        __syncthreads();
    }

    // transform: t = v + bias + res; accumulate row partials
    float psum[4] = {}, psq[4] = {};
    #pragma unroll
    for (int mi = 0; mi < MI; mi++) {
        #pragma unroll
        for (int ni = 0; ni < NI; ni++) {
            #pragma unroll
            for (int ri = 0; ri < 2; ri++) {
                const int row = mi * 16 + ri * 8 + lr;
                const int n = wn0 + ni * 8 + lc * 2;
                long o = (long)(bm + row) * 512 + n;
                float t0 = acc[mi][ni][ri * 2 + 0] + bias[n]     + res[o];
                float t1 = acc[mi][ni][ri * 2 + 1] + bias[n + 1] + res[o + 1];
                acc[mi][ni][ri * 2 + 0] = t0;
                acc[mi][ni][ri * 2 + 1] = t1;
                const int slot = mi * 2 + ri;
                psum[slot] += t0 + t1;
                psq[slot]  += t0 * t0 + t1 * t1;
            }
        }
    }
    #pragma unroll
    for (int i = 0; i < 4; i++) {
        psum[i] += __shfl_xor_sync(0xFFFFFFFFu, psum[i], 1);
        psum[i] += __shfl_xor_sync(0xFFFFFFFFu, psum[i], 2);
        psq[i]  += __shfl_xor_sync(0xFFFFFFFFu, psq[i], 1);
        psq[i]  += __shfl_xor_sync(0xFFFFFFFFu, psq[i], 2);
    }
    if (lc == 0) {
        #pragma unroll
        for (int i = 0; i < 4; i++) {
            const int row = (i >> 1) * 16 + (i & 1) * 8 + lr;
            sred[warp][row]  = psum[i];
            sqred[warp][row] = psq[i];
        }
    }
    __syncthreads();
    if (tid < 32) {
        float s = 0.0f, q = 0.0f;
        #pragma unroll
        for (int w2 = 0; w2 < 8; w2++) { s += sred[w2][tid]; q += sqred[w2][tid]; }
        const float mean = s * (1.0f / 512.0f);
        const float var  = q * (1.0f / 512.0f) - mean * mean;
        smean[tid] = mean;
        sinv[tid]  = rsqrtf(var + LN_EPS);
    }
    __syncthreads();

    #pragma unroll
    for (int mi = 0; mi < MI; mi++) {
        #pragma unroll
        for (int ni = 0; ni < NI; ni++) {
            #pragma unroll
            for (int ri = 0; ri < 2; ri++) {
                const int row = mi * 16 + ri * 8 + lr;
                const int n = wn0 + ni * 8 + lc * 2;
                const float mean = smean[row], inv = sinv[row];
                long o = (long)(bm + row) * 512 + n;
                float o0 = (acc[mi][ni][ri * 2 + 0] - mean) * inv * g[n]     + be[n];
                float o1 = (acc[mi][ni][ri * 2 + 1] - mean) * inv * g[n + 1] + be[n + 1];
                outF[o]     = o0;
                outF[o + 1] = o1;
                *reinterpret_cast<__half2*>(outH + o) = __floats2half2_rn(o0, o1);
            }
        }
    }
}

// ---------------------------------------------------------------------------
// Flash attention: q-tile 128 (8 warps x 16 rows), KV j-tiles of 64 rows,
// 16 iterations, double-buffered, 2 CTAs/SM.
// ---------------------------------------------------------------------------
static constexpr int FA_STR = 72;
static constexpr int FA_KSZ = 64 * FA_STR;
static constexpr int FA_VSZ = 64 * FA_STR;
static constexpr int FA_STAGE = FA_KSZ + FA_VSZ;
static constexpr int FA_PWARP = 16 * FA_STR;
static constexpr int FA_SMEM = (2 * FA_STAGE + 8 * FA_PWARP) * 2;  // 55296 B

__global__ __launch_bounds__(256, 2)
void flash_k(const __half* __restrict__ Q, const __half* __restrict__ Kt,
             const __half* __restrict__ Vt, __half* __restrict__ O)
{
    extern __shared__ __align__(16) __half smh[];
    __half* kv = smh;
    __half* pb = smh + 2 * FA_STAGE;

    const int bh = blockIdx.y;
    const int qt = blockIdx.x;
    const int tid = threadIdx.x, lane = tid & 31, w = tid >> 5;
    const int lr = lane >> 2, lc = lane & 3;
    const int arow = lane & 15, acol = (lane >> 4) << 3;
    const int brow = ((lane >> 4) << 3) + (lane & 7);
    const int bcol = ((lane >> 3) & 1) << 3;
    const long base = (long)bh * S_ * DH_;

    auto loadkv = [&](int j) {
        __half* ks = kv + (j & 1) * FA_STAGE;
        __half* vs = ks + FA_KSZ;
        const __half* kg = Kt + base + (long)j * 64 * 64;
        const __half* vg = Vt + base + (long)j * 64;
        #pragma unroll
        for (int c = tid; c < 512; c += 256) {
            int r = c >> 3, q = (c & 7) * 8;
            cpa16(smem_u32(ks + r * FA_STR + q), kg + r * 64 + q);
        }
        #pragma unroll
        for (int c = tid; c < 512; c += 256) {
            int r = c >> 3, q = (c & 7) * 8;
            cpa16(smem_u32(vs + r * FA_STR + q), vg + (long)r * 1024 + q);
        }
        cp_commit();
    };

    loadkv(0);

    {
        const __half* qg = Q + base + (long)qt * 128 * 64;
        #pragma unroll
        for (int c = tid; c < 1024; c += 256) {
            int r = c >> 3, q = (c & 7) * 8;
            *reinterpret_cast<uint4*>(pb + r * FA_STR + q) =
                *reinterpret_cast<const uint4*>(qg + r * 64 + q);
        }
    }
    __syncthreads();
    uint32_t qf[4][4];
    #pragma unroll
    for (int kk = 0; kk < 4; kk++)
        ldsm4(qf[kk][0], qf[kk][1], qf[kk][2], qf[kk][3],
              smem_u32(pb + (w * 16 + arow) * FA_STR + kk * 16 + acol));

    float m0 = -1e30f, m1 = -1e30f, l0 = 0.0f, l1 = 0.0f;
    float oacc[8][4] = {};
    __half* pw = pb + w * FA_PWARP;

    for (int j = 0; j < 16; j++) {
        if (j + 1 < 16) { loadkv(j + 1); cp_wait<1>(); }
        else            { cp_wait<0>(); }
        __syncthreads();

        const __half* ks = kv + (j & 1) * FA_STAGE;
        const __half* vs = ks + FA_KSZ;

        float sacc[8][4];
        #pragma unroll
        for (int ni = 0; ni < 8; ni++)
            #pragma unroll
            for (int q = 0; q < 4; q++) sacc[ni][q] = 0.0f;
        #pragma unroll
        for (int kk = 0; kk < 4; kk++) {
            #pragma unroll
            for (int ni = 0; ni < 8; ni += 2) {
                uint32_t b00, b01, b10, b11;
                ldsm4(b00, b01, b10, b11,
                      smem_u32(ks + (ni * 8 + brow) * FA_STR + kk * 16 + bcol));
                uint32_t bf0[2] = {b00, b01}, bf1[2] = {b10, b11};
                mma16(sacc[ni], qf[kk], bf0);
                mma16(sacc[ni + 1], qf[kk], bf1);
            }
        }

        float mx0 = -1e30f, mx1 = -1e30f;
        #pragma unroll
        for (int ni = 0; ni < 8; ni++) {
            mx0 = fmaxf(mx0, fmaxf(sacc[ni][0], sacc[ni][1]));
            mx1 = fmaxf(mx1, fmaxf(sacc[ni][2], sacc[ni][3]));
        }
        mx0 = fmaxf(mx0, __shfl_xor_sync(0xFFFFFFFFu, mx0, 1));
        mx0 = fmaxf(mx0, __shfl_xor_sync(0xFFFFFFFFu, mx0, 2));
        mx1 = fmaxf(mx1, __shfl_xor_sync(0xFFFFFFFFu, mx1, 1));
        mx1 = fmaxf(mx1, __shfl_xor_sync(0xFFFFFFFFu, mx1, 2));
        const float mn0 = fmaxf(m0, mx0), mn1 = fmaxf(m1, mx1);
        const float al0 = __expf(m0 - mn0), al1 = __expf(m1 - mn1);

        float rs0 = 0.0f, rs1 = 0.0f;
        #pragma unroll
        for (int ni = 0; ni < 8; ni++) {
            float p0 = __expf(sacc[ni][0] - mn0);
            float p1 = __expf(sacc[ni][1] - mn0);
            float p2 = __expf(sacc[ni][2] - mn1);
            float p3 = __expf(sacc[ni][3] - mn1);
            rs0 += p0 + p1; rs1 += p2 + p3;
            const int col = ni * 8 + 2 * lc;
            *reinterpret_cast<__half2*>(pw + lr * FA_STR + col)       = __floats2half2_rn(p0, p1);
            *reinterpret_cast<__half2*>(pw + (lr + 8) * FA_STR + col) = __floats2half2_rn(p2, p3);
        }
        rs0 += __shfl_xor_sync(0xFFFFFFFFu, rs0, 1);
        rs0 += __shfl_xor_sync(0xFFFFFFFFu, rs0, 2);
        rs1 += __shfl_xor_sync(0xFFFFFFFFu, rs1, 1);
        rs1 += __shfl_xor_sync(0xFFFFFFFFu, rs1, 2);
        m0 = mn0; m1 = mn1;
        l0 = l0 * al0 + rs0;
        l1 = l1 * al1 + rs1;
        #pragma unroll
        for (int ni = 0; ni < 8; ni++) {
            oacc[ni][0] *= al0; oacc[ni][1] *= al0;
            oacc[ni][2] *= al1; oacc[ni][3] *= al1;
        }
        __syncwarp();

        #pragma unroll
        for (int kk2 = 0; kk2 < 4; kk2++) {
            uint32_t af[4];
            ldsm4(af[0], af[1], af[2], af[3],
                  smem_u32(pw + arow * FA_STR + kk2 * 16 + acol));
            #pragma unroll
            for (int ni = 0; ni < 8; ni += 2) {
                uint32_t b00, b01, b10, b11;
                ldsm4(b00, b01, b10, b11,
                      smem_u32(vs + (ni * 8 + brow) * FA_STR + kk2 * 16 + bcol));
                uint32_t bf0[2] = {b00, b01}, bf1[2] = {b10, b11};
                mma16(oacc[ni], af, bf0);
                mma16(oacc[ni + 1], af, bf1);
            }
        }
        __syncthreads();
    }

    const float inv0 = 1.0f / l0, inv1 = 1.0f / l1;
    const int b = bh >> 3, h = bh & 7;
    const int r0 = qt * 128 + w * 16 + lr;
    #pragma unroll
    for (int ni = 0; ni < 8; ni++) {
        const int n = h * 64 + ni * 8 + 2 * lc;
        long o0 = ((long)(b * S_ + r0)) * D_ + n;
        long o1 = ((long)(b * S_ + r0 + 8)) * D_ + n;
        *reinterpret_cast<__half2*>(O + o0) = __floats2half2_rn(oacc[ni][0] * inv0, oacc[ni][1] * inv0);
        *reinterpret_cast<__half2*>(O + o1) = __floats2half2_rn(oacc[ni][2] * inv1, oacc[ni][3] * inv1);
    }
}

// ---------------------------------------------------------------------------
// Merged weight prep: transpose + fp16 convert all six weights in one launch.
// ---------------------------------------------------------------------------
__global__ __launch_bounds__(256) void prep_all(
    const float* __restrict__ wq, const float* __restrict__ wk,
    const float* __restrict__ wv, const float* __restrict__ wo,
    const float* __restrict__ w1, const float* __restrict__ w2,
    __half* __restrict__ out)
{
    __shared__ float t[32][33];
    const int id = blockIdx.x;
    const float* src; __half* dst; int K, N, ki, ni;
    if (id < 8192) {
        const int wsel = id >> 11, rem = id & 2047;
        const int layer = rem >> 8, tile = rem & 255;
        K = 512; N = 512; ki = tile >> 4; ni = tile & 15;
        src = (wsel == 0 ? wq : wsel == 1 ? wk : wsel == 2 ? wv : wo) + (long)layer * 262144;
        dst = out + (wsel < 3 ? OFF_TQKV + (long)layer * SZ_QKV + (long)wsel * 262144
                              : OFF_TO + (long)layer * SZ_O);
    } else if (id < 16384) {
        const int rem = id - 8192, layer = rem >> 10, tile = rem & 1023;
        K = 512; N = 2048; ki = tile >> 6; ni = tile & 63;
        src = w1 + (long)layer * 1048576;
        dst = out + OFF_T1 + (long)layer * SZ_1;
    } else {
        const int rem = id - 16384, layer = rem >> 10, tile = rem & 1023;
        K = 2048; N = 512; ki = tile >> 4; ni = tile & 15;
        src = w2 + (long)layer * 1048576;
        dst = out + OFF_T2 + (long)layer * SZ_2;
    }
    const int k0 = ki * 32, n0 = ni * 32;
    #pragma unroll
    for (int i = threadIdx.y; i < 32; i += 8)
        t[i][threadIdx.x] = src[(long)(k0 + i) * N + n0 + threadIdx.x];
    __syncthreads();
    #pragma unroll
    for (int i = threadIdx.y; i < 32; i += 8)
        dst[(long)(n0 + i) * K + k0 + threadIdx.x] = __float2half_rn(t[threadIdx.x][i]);
}

// copy x -> gx (fp32) and gxh (half)
__global__ __launch_bounds__(256) void copy_half(const float* __restrict__ x,
                                                 float* __restrict__ gx,
                                                 __half* __restrict__ gxh, int n4)
{
    int i = blockIdx.x * blockDim.x + threadIdx.x;
    int stride = gridDim.x * blockDim.x;
    for (; i < n4; i += stride) {
        float4 v = reinterpret_cast<const float4*>(x)[i];
        reinterpret_cast<float4*>(gx)[i] = v;
        reinterpret_cast<__half2*>(gxh)[2 * i]     = __floats2half2_rn(v.x, v.y);
        reinterpret_cast<__half2*>(gxh)[2 * i + 1] = __floats2half2_rn(v.z, v.w);
    }
}

// ---------------------------------------------------------------------------
// Host driver
// ---------------------------------------------------------------------------
extern "C" void kernel_launch(void* const* d_in, const int* in_sizes, int n_in,
                              void* d_out, int out_size)
{
    const float* x   = (const float*)d_in[0];
    const float* wq  = (const float*)d_in[1];
    const float* bq  = (const float*)d_in[2];
    const float* wk  = (const float*)d_in[3];
    const float* bk  = (const float*)d_in[4];
    const float* wv  = (const float*)d_in[5];
    const float* bv  = (const float*)d_in[6];
    const float* wo  = (const float*)d_in[7];
    const float* bo  = (const float*)d_in[8];
    const float* g1  = (const float*)d_in[9];
    const float* be1 = (const float*)d_in[10];
    const float* w1  = (const float*)d_in[11];
    const float* b1  = (const float*)d_in[12];
    const float* w2  = (const float*)d_in[13];
    const float* b2  = (const float*)d_in[14];
    const float* g2  = (const float*)d_in[15];
    const float* be2 = (const float*)d_in[16];

    float* gx;
    __half *gxh, *gqkv, *gattn, *gffn, *gwH;
    cudaGetSymbolAddress((void**)&gx,    g_x);
    cudaGetSymbolAddress((void**)&gxh,   g_xh);
    cudaGetSymbolAddress((void**)&gqkv,  g_qkv);
    cudaGetSymbolAddress((void**)&gattn, g_attn);
    cudaGetSymbolAddress((void**)&gffn,  g_ffn);
    cudaGetSymbolAddress((void**)&gwH,   g_wH);

    constexpr int SM_BIG = smem_bytes<128, 128>();   // 61440
    (void)cudaFuncSetAttribute(mma_gemm<128,128,M_QKV>,  cudaFuncAttributeMaxDynamicSharedMemorySize, SM_BIG);
    (void)cudaFuncSetAttribute(mma_gemm<128,128,M_GELU>, cudaFuncAttributeMaxDynamicSharedMemorySize, SM_BIG);
    (void)cudaFuncSetAttribute(gemm_ln, cudaFuncAttributeMaxDynamicSharedMemorySize, LN_SMEM);
    (void)cudaFuncSetAttribute(flash_k, cudaFuncAttributeMaxDynamicSharedMemorySize, FA_SMEM);

    copy_half<<<512, 256>>>(x, gx, gxh, M_ROWS * D_ / 4);
    prep_all<<<24576, dim3(32, 8)>>>(wq, wk, wv, wo, w1, w2, gwH);

    const __half* gq  = gqkv;
    const __half* gk  = gqkv + MD;
    const __half* gvT = gqkv + 2 * MD;

    const dim3 gQKV(1536 / 128, M_ROWS / 128);   // (12, 32)
    const dim3 gF1(2048 / 128, M_ROWS / 128);    // (16, 32)
    const dim3 gFA(S_ / 128, B_ * H_);           // (8, 32)
    const int  gLN = M_ROWS / 32;                // 128 CTAs

    for (int l = 0; l < L_; l++) {
        const __half* wqkvH_l = gwH + OFF_TQKV + (long)l * SZ_QKV;
        const __half* woH_l   = gwH + OFF_TO   + (long)l * SZ_O;
        const __half* w1H_l   = gwH + OFF_T1   + (long)l * SZ_1;
        const __half* w2H_l   = gwH + OFF_T2   + (long)l * SZ_2;
        const float* bq_l = bq + (long)l * D_;
        const float* bk_l = bk + (long)l * D_;
        const float* bv_l = bv + (long)l * D_;
        const float* bo_l = bo + (long)l * D_;
        const float* b1_l = b1 + (long)l * F_;
        const float* b2_l = b2 + (long)l * D_;
        const float* g1_l = g1 + (long)l * D_;
        const float* g2_l = g2 + (long)l * D_;
        const float* be1_l = be1 + (long)l * D_;
        const float* be2_l = be2 + (long)l * D_;

        // fused QKV projection -> q,k [B,H,S,DH], vT [B,H,DH,S] (half)
        mma_gemm<128,128,M_QKV><<<gQKV, 128, SM_BIG>>>(
            gxh, wqkvH_l, bq_l, bk_l, bv_l, gqkv, 1536, 512);

        // fused attention
        flash_k<<<gFA, 256, FA_SMEM>>>(gq, gk, gvT, gattn);

        // O projection + bias + residual + LN1 (fused)
        gemm_ln<<<gLN, 256, LN_SMEM>>>(
            gattn, woH_l, bo_l, gx, g1_l, be1_l, gx, gxh, 512);

        // FFN1 + GELU (half out)
        mma_gemm<128,128,M_GELU><<<gF1, 128, SM_BIG>>>(
            gxh, w1H_l, b1_l, nullptr, nullptr, gffn, 2048, 512);

        // FFN2 + bias + residual + LN2 (fused)
        gemm_ln<<<gLN, 256, LN_SMEM>>>(
            gffn, w2H_l, b2_l, gx, g2_l, be2_l,
            (l == L_ - 1) ? (float*)d_out : gx, gxh, 2048);
    }
}

// round 11
// speedup vs baseline: 1.1353x; 1.1353x over previous
#include <cuda_runtime.h>
#include <cuda_fp16.h>
#include <math.h>
#include <stdint.h>

// Problem constants
static constexpr int B_ = 4, S_ = 1024, D_ = 512, H_ = 8, F_ = 2048, DH_ = 64, L_ = 8;
static constexpr int M_ROWS = B_ * S_;           // 4096
static constexpr float QK_SCALE = 0.125f;        // 1/sqrt(64)
static constexpr float LN_EPS = 1e-5f;

static constexpr long MD = (long)M_ROWS * D_;    // 2097152
// transposed half weight slabs: [N,K] row-major per layer
static constexpr long SZ_QKV = 1536L * 512, SZ_O = 512L * 512, SZ_1 = 2048L * 512, SZ_2 = 512L * 2048;
static constexpr long OFF_TQKV = 0, OFF_TO = 8 * SZ_QKV, OFF_T1 = OFF_TO + 8 * SZ_O, OFF_T2 = OFF_T1 + 8 * SZ_1;

// Scratch (device globals; no allocation anywhere)
__device__ float g_x[M_ROWS * D_];                          // exact fp32 residual stream
__device__ __align__(16) __half g_xh[M_ROWS * D_];          // half copy for GEMM A
__device__ __align__(16) __half g_qkv[3 * M_ROWS * D_];     // q,k [B,H,S,DH]; vT [B,H,DH,S]
__device__ __align__(16) __half g_attn[M_ROWS * D_];
__device__ float g_tmp[M_ROWS * D_];
__device__ __align__(16) __half g_ffn[M_ROWS * F_];
__device__ __align__(16) __half g_wH[8 * (SZ_QKV + SZ_O + SZ_1 + SZ_2)];   // ~50 MB

enum { M_RES = 2, M_GELU = 3, M_QKV = 6 };

// ---------------------------------------------------------------------------
// helpers
// ---------------------------------------------------------------------------
__device__ __forceinline__ void cpa16(uint32_t smem, const void* gptr) {
    asm volatile("cp.async.cg.shared.global [%0], [%1], 16;\n" :: "r"(smem), "l"(gptr));
}
__device__ __forceinline__ void cp_commit() {
    asm volatile("cp.async.commit_group;\n" ::);
}
template <int N>
__device__ __forceinline__ void cp_wait() {
    asm volatile("cp.async.wait_group %0;\n" :: "n"(N));
}
__device__ __forceinline__ uint32_t smem_u32(const void* p) {
    return (uint32_t)__cvta_generic_to_shared(p);
}

__device__ __forceinline__ void ldsm4(uint32_t& r0, uint32_t& r1, uint32_t& r2,
                                      uint32_t& r3, uint32_t addr) {
    asm volatile("ldmatrix.sync.aligned.m8n8.x4.shared.b16 {%0,%1,%2,%3}, [%4];"
                 : "=r"(r0), "=r"(r1), "=r"(r2), "=r"(r3) : "r"(addr));
}

// m16n8k16 f16 mma, fp32 accumulate
__device__ __forceinline__ void mma16(float* c, const uint32_t* a, const uint32_t* b) {
    asm("mma.sync.aligned.m16n8k16.row.col.f32.f16.f16.f32 "
        "{%0,%1,%2,%3}, {%4,%5,%6,%7}, {%8,%9}, {%0,%1,%2,%3};"
        : "+f"(c[0]), "+f"(c[1]), "+f"(c[2]), "+f"(c[3])
        : "r"(a[0]), "r"(a[1]), "r"(a[2]), "r"(a[3]), "r"(b[0]), "r"(b[1]));
}

// ---------------------------------------------------------------------------
// fp16 mma GEMM: 128 threads, 4 warps of 64x(BN/2), BK=32, 3-stage cp.async.
// C[m,n] = A[m,k] (half, row-major) * Bt[n,k] (half, row-major)^T
// ---------------------------------------------------------------------------
static constexpr int G_ASTR = 40;  // halfs per row (32 + 8 pad)
template <int BM, int BN>
static constexpr int smem_bytes() { return 3 * (BM + BN) * G_ASTR * 2; }

template <int BM, int BN, int MODE>
__global__ __launch_bounds__(128)
void mma_gemm(const __half* __restrict__ A, const __half* __restrict__ Bm,
              const float* __restrict__ b0, const float* __restrict__ b1,
              const float* __restrict__ b2, const float* __restrict__ res,
              float* __restrict__ Cf, __half* __restrict__ Ch, int N, int K)
{
    constexpr int BK = 32;
    constexpr int WM = 64, WN = BN / 2;
    constexpr int MI = WM / 16, NI = WN / 8;     // 4, (8|4)
    constexpr int ASZ = BM * G_ASTR;
    constexpr int BSZ = BN * G_ASTR;

    extern __shared__ __align__(16) __half smh[];
    __half* As = smh;
    __half* Bs = smh + 3 * ASZ;

    const int bm = blockIdx.y * BM;
    const int bn = blockIdx.x * BN;
    const int tid = threadIdx.x;
    const int lane = tid & 31;
    const int warp = tid >> 5;
    const int wm0 = (warp >> 1) * WM;
    const int wn0 = (warp & 1) * WN;
    const int lr = lane >> 2;
    const int lc = lane & 3;
    const int arow = lane & 15, acol = (lane >> 4) << 3;
    const int brow = ((lane >> 4) << 3) + (lane & 7);
    const int bcol = ((lane >> 3) & 1) << 3;

    float acc[MI][NI][4];
    #pragma unroll
    for (int i = 0; i < MI; i++)
        #pragma unroll
        for (int j = 0; j < NI; j++)
            #pragma unroll
            for (int q = 0; q < 4; q++) acc[i][j][q] = 0.0f;

    auto load_stage = [&](int j) {
        const int st = j % 3;
        __half* as = As + st * ASZ;
        #pragma unroll
        for (int c = tid; c < BM * 4; c += 128) {
            int r = c >> 2, q = (c & 3) * 8;
            cpa16(smem_u32(as + r * G_ASTR + q), A + (long)(bm + r) * K + j * BK + q);
        }
        __half* bs = Bs + st * BSZ;
        #pragma unroll
        for (int c = tid; c < BN * 4; c += 128) {
            int r = c >> 2, q = (c & 3) * 8;
            cpa16(smem_u32(bs + r * G_ASTR + q), Bm + (long)(bn + r) * K + j * BK + q);
        }
        cp_commit();
    };

    const int NIT = K / BK;
    load_stage(0);
    if (NIT > 1) load_stage(1);

    for (int it = 0; it < NIT; it++) {
        if (it + 2 < NIT) { load_stage(it + 2); cp_wait<2>(); }
        else if (it + 2 == NIT) { cp_wait<1>(); }
        else { cp_wait<0>(); }
        __syncthreads();

        const int st = it % 3;
        const __half* as = As + st * ASZ;
        const __half* bs = Bs + st * BSZ;
        #pragma unroll
        for (int kk = 0; kk < BK; kk += 16) {
            uint32_t af[MI][4];
            #pragma unroll
            for (int mi = 0; mi < MI; mi++)
                ldsm4(af[mi][0], af[mi][1], af[mi][2], af[mi][3],
                      smem_u32(as + (wm0 + mi * 16 + arow) * G_ASTR + kk + acol));
            uint32_t bf[NI][2];
            #pragma unroll
            for (int ni = 0; ni < NI; ni += 2)
                ldsm4(bf[ni][0], bf[ni][1], bf[ni + 1][0], bf[ni + 1][1],
                      smem_u32(bs + (wn0 + ni * 8 + brow) * G_ASTR + kk + bcol));
            #pragma unroll
            for (int mi = 0; mi < MI; mi++)
                #pragma unroll
                for (int ni = 0; ni < NI; ni++)
                    mma16(acc[mi][ni], af[mi], bf[ni]);
        }
        __syncthreads();
    }

    #pragma unroll
    for (int mi = 0; mi < MI; mi++) {
        #pragma unroll
        for (int ni = 0; ni < NI; ni++) {
            #pragma unroll
            for (int ri = 0; ri < 2; ri++) {
                const int m = bm + wm0 + mi * 16 + lr + ri * 8;
                const int n = bn + wn0 + ni * 8 + lc * 2;
                float v0 = acc[mi][ni][ri * 2 + 0];
                float v1 = acc[mi][ni][ri * 2 + 1];
                if (MODE == M_RES) {
                    long o = (long)m * N + n;
                    Cf[o]     = v0 + b0[n]     + res[o];
                    Cf[o + 1] = v1 + b0[n + 1] + res[o + 1];
                } else if (MODE == M_GELU) {
                    v0 += b0[n]; v1 += b0[n + 1];
                    float g0 = 0.5f * v0 * (1.0f + erff(v0 * 0.70710678118654752f));
                    float g1 = 0.5f * v1 * (1.0f + erff(v1 * 0.70710678118654752f));
                    *reinterpret_cast<__half2*>(Ch + (long)m * N + n) = __floats2half2_rn(g0, g1);
                } else { // M_QKV
                    const int t = n >> 9;
                    const int colD = n & 511;
                    const float* bb = (t == 0) ? b0 : ((t == 1) ? b1 : b2);
                    const int b = m >> 10, s = m & 1023, h = colD >> 6, dh0 = colD & 63;
                    const int bh = (b << 3) + h;
                    float u0 = v0 + bb[colD], u1 = v1 + bb[colD + 1];
                    if (t == 0) { u0 *= QK_SCALE; u1 *= QK_SCALE; }
                    if (t == 2) {
                        long o = 2 * MD + ((long)bh << 16) + ((long)dh0 << 10) + s;
                        Ch[o]        = __float2half_rn(u0);
                        Ch[o + 1024] = __float2half_rn(u1);
                    } else {
                        long o = (long)t * MD + (((long)bh * S_ + s) << 6) + dh0;
                        *reinterpret_cast<__half2*>(Ch + o) = __floats2half2_rn(u0, u1);
                    }
                }
            }
        }
    }
}

// ---------------------------------------------------------------------------
// Flash attention: q-tile 128 (8 warps x 16 rows), KV j-tiles of 64 rows,
// 16 iterations, double-buffered. 2 CTAs/SM (regs clamped to 128).
// Q,K: [B,H,S,DH] half (Q pre-scaled). Vt: [B,H,DH,S] half.
// ---------------------------------------------------------------------------
static constexpr int FA_STR = 72;                     // halfs (64 + 8 pad)
static constexpr int FA_KSZ = 64 * FA_STR;            // 4608 halfs per K tile
static constexpr int FA_VSZ = 64 * FA_STR;            // 4608 halfs per V tile
static constexpr int FA_STAGE = FA_KSZ + FA_VSZ;      // 9216 halfs
static constexpr int FA_PWARP = 16 * FA_STR;          // 1152 halfs per warp
static constexpr int FA_SMEM = (2 * FA_STAGE + 8 * FA_PWARP) * 2;  // 55296 B

__global__ __launch_bounds__(256, 2)
void flash_k(const __half* __restrict__ Q, const __half* __restrict__ Kt,
             const __half* __restrict__ Vt, __half* __restrict__ O)
{
    extern __shared__ __align__(16) __half smh[];
    __half* kv = smh;
    __half* pb = smh + 2 * FA_STAGE;    // P region; also Q staging (128 x 72 = 9216)

    const int bh = blockIdx.y;
    const int qt = blockIdx.x;
    const int tid = threadIdx.x, lane = tid & 31, w = tid >> 5;
    const int lr = lane >> 2, lc = lane & 3;
    const int arow = lane & 15, acol = (lane >> 4) << 3;
    const int brow = ((lane >> 4) << 3) + (lane & 7);
    const int bcol = ((lane >> 3) & 1) << 3;
    const long base = (long)bh * S_ * DH_;

    auto loadkv = [&](int j) {               // j in [0,16): 64 s-rows
        __half* ks = kv + (j & 1) * FA_STAGE;
        __half* vs = ks + FA_KSZ;
        const __half* kg = Kt + base + (long)j * 64 * 64;    // [s][dh] rows
        const __half* vg = Vt + base + (long)j * 64;         // [dh][s] col slice
        #pragma unroll
        for (int c = tid; c < 512; c += 256) {               // K: 64 rows x 8 chunks
            int r = c >> 3, q = (c & 7) * 8;
            cpa16(smem_u32(ks + r * FA_STR + q), kg + r * 64 + q);
        }
        #pragma unroll
        for (int c = tid; c < 512; c += 256) {               // V: 64 dh-rows x 8 chunks
            int r = c >> 3, q = (c & 7) * 8;
            cpa16(smem_u32(vs + r * FA_STR + q), vg + (long)r * 1024 + q);
        }
        cp_commit();
    };

    loadkv(0);

    // Stage Q tile (128 x 64 halfs, stride FA_STR) in P region; grab fragments.
    {
        const __half* qg = Q + base + (long)qt * 128 * 64;
        #pragma unroll
        for (int c = tid; c < 1024; c += 256) {
            int r = c >> 3, q = (c & 7) * 8;
            *reinterpret_cast<uint4*>(pb + r * FA_STR + q) =
                *reinterpret_cast<const uint4*>(qg + r * 64 + q);
        }
    }
    __syncthreads();
    uint32_t qf[4][4];
    #pragma unroll
    for (int kk = 0; kk < 4; kk++)
        ldsm4(qf[kk][0], qf[kk][1], qf[kk][2], qf[kk][3],
              smem_u32(pb + (w * 16 + arow) * FA_STR + kk * 16 + acol));

    float m0 = -1e30f, m1 = -1e30f, l0 = 0.0f, l1 = 0.0f;
    float oacc[8][4] = {};
    __half* pw = pb + w * FA_PWARP;

    for (int j = 0; j < 16; j++) {
        if (j + 1 < 16) { loadkv(j + 1); cp_wait<1>(); }
        else            { cp_wait<0>(); }
        __syncthreads();   // stage j ready; also protects P/Q region reuse

        const __half* ks = kv + (j & 1) * FA_STAGE;
        const __half* vs = ks + FA_KSZ;

        // S = Q K^T (16 q-rows x 64 s-cols per warp)
        float sacc[8][4];
        #pragma unroll
        for (int ni = 0; ni < 8; ni++)
            #pragma unroll
            for (int q = 0; q < 4; q++) sacc[ni][q] = 0.0f;
        #pragma unroll
        for (int kk = 0; kk < 4; kk++) {
            #pragma unroll
            for (int ni = 0; ni < 8; ni += 2) {
                uint32_t b00, b01, b10, b11;
                ldsm4(b00, b01, b10, b11,
                      smem_u32(ks + (ni * 8 + brow) * FA_STR + kk * 16 + bcol));
                uint32_t bf0[2] = {b00, b01}, bf1[2] = {b10, b11};
                mma16(sacc[ni], qf[kk], bf0);
                mma16(sacc[ni + 1], qf[kk], bf1);
            }
        }

        // online softmax over this 64-col block
        float mx0 = -1e30f, mx1 = -1e30f;
        #pragma unroll
        for (int ni = 0; ni < 8; ni++) {
            mx0 = fmaxf(mx0, fmaxf(sacc[ni][0], sacc[ni][1]));
            mx1 = fmaxf(mx1, fmaxf(sacc[ni][2], sacc[ni][3]));
        }
        mx0 = fmaxf(mx0, __shfl_xor_sync(0xFFFFFFFFu, mx0, 1));
        mx0 = fmaxf(mx0, __shfl_xor_sync(0xFFFFFFFFu, mx0, 2));
        mx1 = fmaxf(mx1, __shfl_xor_sync(0xFFFFFFFFu, mx1, 1));
        mx1 = fmaxf(mx1, __shfl_xor_sync(0xFFFFFFFFu, mx1, 2));
        const float mn0 = fmaxf(m0, mx0), mn1 = fmaxf(m1, mx1);
        const float al0 = __expf(m0 - mn0), al1 = __expf(m1 - mn1);

        float rs0 = 0.0f, rs1 = 0.0f;
        #pragma unroll
        for (int ni = 0; ni < 8; ni++) {
            float p0 = __expf(sacc[ni][0] - mn0);
            float p1 = __expf(sacc[ni][1] - mn0);
            float p2 = __expf(sacc[ni][2] - mn1);
            float p3 = __expf(sacc[ni][3] - mn1);
            rs0 += p0 + p1; rs1 += p2 + p3;
            const int col = ni * 8 + 2 * lc;
            *reinterpret_cast<__half2*>(pw + lr * FA_STR + col)       = __floats2half2_rn(p0, p1);
            *reinterpret_cast<__half2*>(pw + (lr + 8) * FA_STR + col) = __floats2half2_rn(p2, p3);
        }
        rs0 += __shfl_xor_sync(0xFFFFFFFFu, rs0, 1);
        rs0 += __shfl_xor_sync(0xFFFFFFFFu, rs0, 2);
        rs1 += __shfl_xor_sync(0xFFFFFFFFu, rs1, 1);
        rs1 += __shfl_xor_sync(0xFFFFFFFFu, rs1, 2);
        m0 = mn0; m1 = mn1;
        l0 = l0 * al0 + rs0;
        l1 = l1 * al1 + rs1;
        #pragma unroll
        for (int ni = 0; ni < 8; ni++) {
            oacc[ni][0] *= al0; oacc[ni][1] *= al0;
            oacc[ni][2] *= al1; oacc[ni][3] *= al1;
        }
        __syncwarp();

        // O += P V : P (16 x 64) A-operand; Vt smem [dh][s-slice] = B [n][k]
        #pragma unroll
        for (int kk2 = 0; kk2 < 4; kk2++) {
            uint32_t af[4];
            ldsm4(af[0], af[1], af[2], af[3],
                  smem_u32(pw + arow * FA_STR + kk2 * 16 + acol));
            #pragma unroll
            for (int ni = 0; ni < 8; ni += 2) {
                uint32_t b00, b01, b10, b11;
                ldsm4(b00, b01, b10, b11,
                      smem_u32(vs + (ni * 8 + brow) * FA_STR + kk2 * 16 + bcol));
                uint32_t bf0[2] = {b00, b01}, bf1[2] = {b10, b11};
                mma16(oacc[ni], af, bf0);
                mma16(oacc[ni + 1], af, bf1);
            }
        }
        __syncthreads();  // before next loadkv overwrites a stage
    }

    // epilogue: divide by l, write [B,S,D] half
    const float inv0 = 1.0f / l0, inv1 = 1.0f / l1;
    const int b = bh >> 3, h = bh & 7;
    const int r0 = qt * 128 + w * 16 + lr;
    #pragma unroll
    for (int ni = 0; ni < 8; ni++) {
        const int n = h * 64 + ni * 8 + 2 * lc;
        long o0 = ((long)(b * S_ + r0)) * D_ + n;
        long o1 = ((long)(b * S_ + r0 + 8)) * D_ + n;
        *reinterpret_cast<__half2*>(O + o0) = __floats2half2_rn(oacc[ni][0] * inv0, oacc[ni][1] * inv0);
        *reinterpret_cast<__half2*>(O + o1) = __floats2half2_rn(oacc[ni][2] * inv1, oacc[ni][3] * inv1);
    }
}

// ---------------------------------------------------------------------------
// Merged weight prep: transpose + fp16 convert all six weights in one launch.
// ---------------------------------------------------------------------------
__global__ __launch_bounds__(256) void prep_all(
    const float* __restrict__ wq, const float* __restrict__ wk,
    const float* __restrict__ wv, const float* __restrict__ wo,
    const float* __restrict__ w1, const float* __restrict__ w2,
    __half* __restrict__ out)
{
    __shared__ float t[32][33];
    const int id = blockIdx.x;
    const float* src; __half* dst; int K, N, ki, ni;
    if (id < 8192) {
        const int wsel = id >> 11, rem = id & 2047;
        const int layer = rem >> 8, tile = rem & 255;
        K = 512; N = 512; ki = tile >> 4; ni = tile & 15;
        src = (wsel == 0 ? wq : wsel == 1 ? wk : wsel == 2 ? wv : wo) + (long)layer * 262144;
        dst = out + (wsel < 3 ? OFF_TQKV + (long)layer * SZ_QKV + (long)wsel * 262144
                              : OFF_TO + (long)layer * SZ_O);
    } else if (id < 16384) {
        const int rem = id - 8192, layer = rem >> 10, tile = rem & 1023;
        K = 512; N = 2048; ki = tile >> 6; ni = tile & 63;
        src = w1 + (long)layer * 1048576;
        dst = out + OFF_T1 + (long)layer * SZ_1;
    } else {
        const int rem = id - 16384, layer = rem >> 10, tile = rem & 1023;
        K = 2048; N = 512; ki = tile >> 4; ni = tile & 15;
        src = w2 + (long)layer * 1048576;
        dst = out + OFF_T2 + (long)layer * SZ_2;
    }
    const int k0 = ki * 32, n0 = ni * 32;
    #pragma unroll
    for (int i = threadIdx.y; i < 32; i += 8)
        t[i][threadIdx.x] = src[(long)(k0 + i) * N + n0 + threadIdx.x];
    __syncthreads();
    #pragma unroll
    for (int i = threadIdx.y; i < 32; i += 8)
        dst[(long)(n0 + i) * K + k0 + threadIdx.x] = __float2half_rn(t[threadIdx.x][i]);
}

// copy x -> gx (fp32) and gxh (half)
__global__ __launch_bounds__(256) void copy_half(const float* __restrict__ x,
                                                 float* __restrict__ gx,
                                                 __half* __restrict__ gxh, int n4)
{
    int i = blockIdx.x * blockDim.x + threadIdx.x;
    int stride = gridDim.x * blockDim.x;
    for (; i < n4; i += stride) {
        float4 v = reinterpret_cast<const float4*>(x)[i];
        reinterpret_cast<float4*>(gx)[i] = v;
        reinterpret_cast<__half2*>(gxh)[2 * i]     = __floats2half2_rn(v.x, v.y);
        reinterpret_cast<__half2*>(gxh)[2 * i + 1] = __floats2half2_rn(v.z, v.w);
    }
}

// ---------------------------------------------------------------------------
// Row LayerNorm over 512 elements; fp32 out + half out_h.
// ---------------------------------------------------------------------------
__global__ __launch_bounds__(128) void ln_k(const float* __restrict__ in,
                                            const float* __restrict__ g,
                                            const float* __restrict__ be,
                                            float* __restrict__ out,
                                            __half* __restrict__ out_h)
{
    const int row = blockIdx.x;
    const int t = threadIdx.x;
    const float4 v = reinterpret_cast<const float4*>(in + (long)row * D_)[t];

    float s  = v.x + v.y + v.z + v.w;
    float sq = v.x * v.x + v.y * v.y + v.z * v.z + v.w * v.w;
    #pragma unroll
    for (int o = 16; o; o >>= 1) {
        s  += __shfl_xor_sync(0xFFFFFFFFu, s, o);
        sq += __shfl_xor_sync(0xFFFFFFFFu, sq, o);
    }
    __shared__ float sh0[4], sh1[4];
    if ((t & 31) == 0) { sh0[t >> 5] = s; sh1[t >> 5] = sq; }
    __syncthreads();
    s  = sh0[0] + sh0[1] + sh0[2] + sh0[3];
    sq = sh1[0] + sh1[1] + sh1[2] + sh1[3];

    const float mean = s * (1.0f / D_);
    const float var  = sq * (1.0f / D_) - mean * mean;
    const float inv  = rsqrtf(var + LN_EPS);

    const float4 gg = reinterpret_cast<const float4*>(g)[t];
    const float4 bb = reinterpret_cast<const float4*>(be)[t];
    float4 o4;
    o4.x = (v.x - mean) * inv * gg.x + bb.x;
    o4.y = (v.y - mean) * inv * gg.y + bb.y;
    o4.z = (v.z - mean) * inv * gg.z + bb.z;
    o4.w = (v.w - mean) * inv * gg.w + bb.w;
    reinterpret_cast<float4*>(out + (long)row * D_)[t] = o4;
    __half2* oh = reinterpret_cast<__half2*>(out_h + (long)row * D_);
    oh[2 * t]     = __floats2half2_rn(o4.x, o4.y);
    oh[2 * t + 1] = __floats2half2_rn(o4.z, o4.w);
}

// ---------------------------------------------------------------------------
// Host driver
// ---------------------------------------------------------------------------
extern "C" void kernel_launch(void* const* d_in, const int* in_sizes, int n_in,
                              void* d_out, int out_size)
{
    const float* x   = (const float*)d_in[0];
    const float* wq  = (const float*)d_in[1];
    const float* bq  = (const float*)d_in[2];
    const float* wk  = (const float*)d_in[3];
    const float* bk  = (const float*)d_in[4];
    const float* wv  = (const float*)d_in[5];
    const float* bv  = (const float*)d_in[6];
    const float* wo  = (const float*)d_in[7];
    const float* bo  = (const float*)d_in[8];
    const float* g1  = (const float*)d_in[9];
    const float* be1 = (const float*)d_in[10];
    const float* w1  = (const float*)d_in[11];
    const float* b1  = (const float*)d_in[12];
    const float* w2  = (const float*)d_in[13];
    const float* b2  = (const float*)d_in[14];
    const float* g2  = (const float*)d_in[15];
    const float* be2 = (const float*)d_in[16];

    float *gx, *gtmp;
    __half *gxh, *gqkv, *gattn, *gffn, *gwH;
    cudaGetSymbolAddress((void**)&gx,    g_x);
    cudaGetSymbolAddress((void**)&gxh,   g_xh);
    cudaGetSymbolAddress((void**)&gqkv,  g_qkv);
    cudaGetSymbolAddress((void**)&gattn, g_attn);
    cudaGetSymbolAddress((void**)&gtmp,  g_tmp);
    cudaGetSymbolAddress((void**)&gffn,  g_ffn);
    cudaGetSymbolAddress((void**)&gwH,   g_wH);

    constexpr int SM_BIG = smem_bytes<128, 128>();   // 61440
    constexpr int SM_SML = smem_bytes<128, 64>();    // 46080
    (void)cudaFuncSetAttribute(mma_gemm<128,128,M_QKV>,  cudaFuncAttributeMaxDynamicSharedMemorySize, SM_BIG);
    (void)cudaFuncSetAttribute(mma_gemm<128,64,M_RES>,   cudaFuncAttributeMaxDynamicSharedMemorySize, SM_SML);
    (void)cudaFuncSetAttribute(mma_gemm<128,128,M_GELU>, cudaFuncAttributeMaxDynamicSharedMemorySize, SM_BIG);
    (void)cudaFuncSetAttribute(flash_k, cudaFuncAttributeMaxDynamicSharedMemorySize, FA_SMEM);

    copy_half<<<512, 256>>>(x, gx, gxh, M_ROWS * D_ / 4);
    prep_all<<<24576, dim3(32, 8)>>>(wq, wk, wv, wo, w1, w2, gwH);

    const __half* gq  = gqkv;
    const __half* gk  = gqkv + MD;
    const __half* gvT = gqkv + 2 * MD;

    const dim3 gQKV(1536 / 128, M_ROWS / 128);   // (12, 32)
    const dim3 gOP(512 / 64, M_ROWS / 128);      // (8, 32) = 256 CTAs
    const dim3 gF1(2048 / 128, M_ROWS / 128);    // (16, 32)
    const dim3 gFA(S_ / 128, B_ * H_);           // (8, 32)

    for (int l = 0; l < L_; l++) {
        const __half* wqkvH_l = gwH + OFF_TQKV + (long)l * SZ_QKV;
        const __half* woH_l   = gwH + OFF_TO   + (long)l * SZ_O;
        const __half* w1H_l   = gwH + OFF_T1   + (long)l * SZ_1;
        const __half* w2H_l   = gwH + OFF_T2   + (long)l * SZ_2;
        const float* bq_l = bq + (long)l * D_;
        const float* bk_l = bk + (long)l * D_;
        const float* bv_l = bv + (long)l * D_;
        const float* bo_l = bo + (long)l * D_;
        const float* b1_l = b1 + (long)l * F_;
        const float* b2_l = b2 + (long)l * D_;
        const float* g1_l = g1 + (long)l * D_;
        const float* g2_l = g2 + (long)l * D_;
        const float* be1_l = be1 + (long)l * D_;
        const float* be2_l = be2 + (long)l * D_;

        // fused QKV projection -> q,k [B,H,S,DH], vT [B,H,DH,S] (half)
        mma_gemm<128,128,M_QKV><<<gQKV, 128, SM_BIG>>>(
            gxh, wqkvH_l, bq_l, bk_l, bv_l, nullptr, nullptr, gqkv, 1536, 512);

        // fused attention
        flash_k<<<gFA, 256, FA_SMEM>>>(gq, gk, gvT, gattn);

        // O projection + bias + residual (fp32 out), BN=64 for full-wave fill
        mma_gemm<128,64,M_RES><<<gOP, 128, SM_SML>>>(
            gattn, woH_l, bo_l, nullptr, nullptr, gx, gtmp, nullptr, 512, 512);
        ln_k<<<M_ROWS, 128>>>(gtmp, g1_l, be1_l, gx, gxh);

        // FFN1 + GELU (half out)
        mma_gemm<128,128,M_GELU><<<gF1, 128, SM_BIG>>>(
            gxh, w1H_l, b1_l, nullptr, nullptr, nullptr, nullptr, gffn, 2048, 512);
        // FFN2 + bias + residual (fp32 out), BN=64
        mma_gemm<128,64,M_RES><<<gOP, 128, SM_SML>>>(
            gffn, w2H_l, b2_l, nullptr, nullptr, gx, gtmp, nullptr, 512, 2048);
        ln_k<<<M_ROWS, 128>>>(gtmp, g2_l, be2_l,
                              (l == L_ - 1) ? (float*)d_out : gx, gxh);
    }
}

// round 12
// speedup vs baseline: 1.1411x; 1.0051x over previous
#include <cuda_runtime.h>
#include <cuda_fp16.h>
#include <math.h>
#include <stdint.h>

// Problem constants
static constexpr int B_ = 4, S_ = 1024, D_ = 512, H_ = 8, F_ = 2048, DH_ = 64, L_ = 8;
static constexpr int M_ROWS = B_ * S_;           // 4096
static constexpr float QK_SCALE = 0.125f;        // 1/sqrt(64)
static constexpr float LN_EPS = 1e-5f;

static constexpr long MD = (long)M_ROWS * D_;    // 2097152
// transposed half weight slabs: [N,K] row-major per layer
static constexpr long SZ_QKV = 1536L * 512, SZ_O = 512L * 512, SZ_1 = 2048L * 512, SZ_2 = 512L * 2048;
static constexpr long OFF_TQKV = 0, OFF_TO = 8 * SZ_QKV, OFF_T1 = OFF_TO + 8 * SZ_O, OFF_T2 = OFF_T1 + 8 * SZ_1;

// Scratch (device globals; no allocation anywhere)
__device__ float g_x[M_ROWS * D_];                          // exact fp32 residual stream
__device__ __align__(16) __half g_xh[M_ROWS * D_];          // half copy for GEMM A
__device__ __align__(16) __half g_qkv[3 * M_ROWS * D_];     // q,k [B,H,S,DH]; vT [B,H,DH,S]
__device__ __align__(16) __half g_attn[M_ROWS * D_];
__device__ float g_tmp[M_ROWS * D_];
__device__ __align__(16) __half g_ffn[M_ROWS * F_];
__device__ __align__(16) __half g_wH[8 * (SZ_QKV + SZ_O + SZ_1 + SZ_2)];   // ~50 MB

enum { M_RES = 2, M_GELU = 3, M_QKV = 6 };

// ---------------------------------------------------------------------------
// helpers
// ---------------------------------------------------------------------------
__device__ __forceinline__ void cpa16(uint32_t smem, const void* gptr) {
    asm volatile("cp.async.cg.shared.global [%0], [%1], 16;\n" :: "r"(smem), "l"(gptr));
}
__device__ __forceinline__ void cp_commit() {
    asm volatile("cp.async.commit_group;\n" ::);
}
template <int N>
__device__ __forceinline__ void cp_wait() {
    asm volatile("cp.async.wait_group %0;\n" :: "n"(N));
}
__device__ __forceinline__ uint32_t smem_u32(const void* p) {
    return (uint32_t)__cvta_generic_to_shared(p);
}

__device__ __forceinline__ void ldsm4(uint32_t& r0, uint32_t& r1, uint32_t& r2,
                                      uint32_t& r3, uint32_t addr) {
    asm volatile("ldmatrix.sync.aligned.m8n8.x4.shared.b16 {%0,%1,%2,%3}, [%4];"
                 : "=r"(r0), "=r"(r1), "=r"(r2), "=r"(r3) : "r"(addr));
}

// m16n8k16 f16 mma, fp32 accumulate
__device__ __forceinline__ void mma16(float* c, const uint32_t* a, const uint32_t* b) {
    asm("mma.sync.aligned.m16n8k16.row.col.f32.f16.f16.f32 "
        "{%0,%1,%2,%3}, {%4,%5,%6,%7}, {%8,%9}, {%0,%1,%2,%3};"
        : "+f"(c[0]), "+f"(c[1]), "+f"(c[2]), "+f"(c[3])
        : "r"(a[0]), "r"(a[1]), "r"(a[2]), "r"(a[3]), "r"(b[0]), "r"(b[1]));
}

// ---------------------------------------------------------------------------
// fp16 mma GEMM: 256 threads, 8 warps (4 m-rows x 2 n-cols), warp tile
// 32 x (BN/2). BK=32, 3-stage cp.async. C[m,n] = A[m,k] * Bt[n,k]^T
// ---------------------------------------------------------------------------
static constexpr int G_ASTR = 40;  // halfs per row (32 + 8 pad)
template <int BM, int BN>
static constexpr int smem_bytes() { return 3 * (BM + BN) * G_ASTR * 2; }

template <int BM, int BN, int MODE>
__global__ __launch_bounds__(256, 2)
void mma_gemm(const __half* __restrict__ A, const __half* __restrict__ Bm,
              const float* __restrict__ b0, const float* __restrict__ b1,
              const float* __restrict__ b2, const float* __restrict__ res,
              float* __restrict__ Cf, __half* __restrict__ Ch, int N, int K)
{
    constexpr int BK = 32;
    constexpr int WM = BM / 4, WN = BN / 2;      // 32 x (64|32)
    constexpr int MI = WM / 16, NI = WN / 8;     // 2, (8|4)
    constexpr int ASZ = BM * G_ASTR;
    constexpr int BSZ = BN * G_ASTR;

    extern __shared__ __align__(16) __half smh[];
    __half* As = smh;
    __half* Bs = smh + 3 * ASZ;

    const int bm = blockIdx.y * BM;
    const int bn = blockIdx.x * BN;
    const int tid = threadIdx.x;
    const int lane = tid & 31;
    const int warp = tid >> 5;                   // 0..7
    const int wm0 = (warp & 3) * WM;
    const int wn0 = (warp >> 2) * WN;
    const int lr = lane >> 2;
    const int lc = lane & 3;
    const int arow = lane & 15, acol = (lane >> 4) << 3;
    const int brow = ((lane >> 4) << 3) + (lane & 7);
    const int bcol = ((lane >> 3) & 1) << 3;

    float acc[MI][NI][4];
    #pragma unroll
    for (int i = 0; i < MI; i++)
        #pragma unroll
        for (int j = 0; j < NI; j++)
            #pragma unroll
            for (int q = 0; q < 4; q++) acc[i][j][q] = 0.0f;

    auto load_stage = [&](int j) {
        const int st = j % 3;
        __half* as = As + st * ASZ;
        #pragma unroll
        for (int c = tid; c < BM * 4; c += 256) {
            int r = c >> 2, q = (c & 3) * 8;
            cpa16(smem_u32(as + r * G_ASTR + q), A + (long)(bm + r) * K + j * BK + q);
        }
        __half* bs = Bs + st * BSZ;
        #pragma unroll
        for (int c = tid; c < BN * 4; c += 256) {
            int r = c >> 2, q = (c & 3) * 8;
            cpa16(smem_u32(bs + r * G_ASTR + q), Bm + (long)(bn + r) * K + j * BK + q);
        }
        cp_commit();
    };

    const int NIT = K / BK;
    load_stage(0);
    if (NIT > 1) load_stage(1);

    for (int it = 0; it < NIT; it++) {
        if (it + 2 < NIT) { load_stage(it + 2); cp_wait<2>(); }
        else if (it + 2 == NIT) { cp_wait<1>(); }
        else { cp_wait<0>(); }
        __syncthreads();

        const int st = it % 3;
        const __half* as = As + st * ASZ;
        const __half* bs = Bs + st * BSZ;
        #pragma unroll
        for (int kk = 0; kk < BK; kk += 16) {
            uint32_t af[MI][4];
            #pragma unroll
            for (int mi = 0; mi < MI; mi++)
                ldsm4(af[mi][0], af[mi][1], af[mi][2], af[mi][3],
                      smem_u32(as + (wm0 + mi * 16 + arow) * G_ASTR + kk + acol));
            uint32_t bf[NI][2];
            #pragma unroll
            for (int ni = 0; ni < NI; ni += 2)
                ldsm4(bf[ni][0], bf[ni][1], bf[ni + 1][0], bf[ni + 1][1],
                      smem_u32(bs + (wn0 + ni * 8 + brow) * G_ASTR + kk + bcol));
            #pragma unroll
            for (int mi = 0; mi < MI; mi++)
                #pragma unroll
                for (int ni = 0; ni < NI; ni++)
                    mma16(acc[mi][ni], af[mi], bf[ni]);
        }
        __syncthreads();
    }

    #pragma unroll
    for (int mi = 0; mi < MI; mi++) {
        #pragma unroll
        for (int ni = 0; ni < NI; ni++) {
            #pragma unroll
            for (int ri = 0; ri < 2; ri++) {
                const int m = bm + wm0 + mi * 16 + lr + ri * 8;
                const int n = bn + wn0 + ni * 8 + lc * 2;
                float v0 = acc[mi][ni][ri * 2 + 0];
                float v1 = acc[mi][ni][ri * 2 + 1];
                if (MODE == M_RES) {
                    long o = (long)m * N + n;
                    Cf[o]     = v0 + b0[n]     + res[o];
                    Cf[o + 1] = v1 + b0[n + 1] + res[o + 1];
                } else if (MODE == M_GELU) {
                    v0 += b0[n]; v1 += b0[n + 1];
                    float g0 = 0.5f * v0 * (1.0f + erff(v0 * 0.70710678118654752f));
                    float g1 = 0.5f * v1 * (1.0f + erff(v1 * 0.70710678118654752f));
                    *reinterpret_cast<__half2*>(Ch + (long)m * N + n) = __floats2half2_rn(g0, g1);
                } else { // M_QKV
                    const int t = n >> 9;
                    const int colD = n & 511;
                    const float* bb = (t == 0) ? b0 : ((t == 1) ? b1 : b2);
                    const int b = m >> 10, s = m & 1023, h = colD >> 6, dh0 = colD & 63;
                    const int bh = (b << 3) + h;
                    float u0 = v0 + bb[colD], u1 = v1 + bb[colD + 1];
                    if (t == 0) { u0 *= QK_SCALE; u1 *= QK_SCALE; }
                    if (t == 2) {
                        long o = 2 * MD + ((long)bh << 16) + ((long)dh0 << 10) + s;
                        Ch[o]        = __float2half_rn(u0);
                        Ch[o + 1024] = __float2half_rn(u1);
                    } else {
                        long o = (long)t * MD + (((long)bh * S_ + s) << 6) + dh0;
                        *reinterpret_cast<__half2*>(Ch + o) = __floats2half2_rn(u0, u1);
                    }
                }
            }
        }
    }
}

// ---------------------------------------------------------------------------
// Flash attention: q-tile 128 (8 warps x 16 rows), KV j-tiles of 64 rows,
// 16 iterations, double-buffered. 2 CTAs/SM (regs clamped to 128).
// Q,K: [B,H,S,DH] half (Q pre-scaled). Vt: [B,H,DH,S] half.
// ---------------------------------------------------------------------------
static constexpr int FA_STR = 72;                     // halfs (64 + 8 pad)
static constexpr int FA_KSZ = 64 * FA_STR;            // 4608 halfs per K tile
static constexpr int FA_VSZ = 64 * FA_STR;            // 4608 halfs per V tile
static constexpr int FA_STAGE = FA_KSZ + FA_VSZ;      // 9216 halfs
static constexpr int FA_PWARP = 16 * FA_STR;          // 1152 halfs per warp
static constexpr int FA_SMEM = (2 * FA_STAGE + 8 * FA_PWARP) * 2;  // 55296 B

__global__ __launch_bounds__(256, 2)
void flash_k(const __half* __restrict__ Q, const __half* __restrict__ Kt,
             const __half* __restrict__ Vt, __half* __restrict__ O)
{
    extern __shared__ __align__(16) __half smh[];
    __half* kv = smh;
    __half* pb = smh + 2 * FA_STAGE;    // P region; also Q staging (128 x 72 = 9216)

    const int bh = blockIdx.y;
    const int qt = blockIdx.x;
    const int tid = threadIdx.x, lane = tid & 31, w = tid >> 5;
    const int lr = lane >> 2, lc = lane & 3;
    const int arow = lane & 15, acol = (lane >> 4) << 3;
    const int brow = ((lane >> 4) << 3) + (lane & 7);
    const int bcol = ((lane >> 3) & 1) << 3;
    const long base = (long)bh * S_ * DH_;

    auto loadkv = [&](int j) {               // j in [0,16): 64 s-rows
        __half* ks = kv + (j & 1) * FA_STAGE;
        __half* vs = ks + FA_KSZ;
        const __half* kg = Kt + base + (long)j * 64 * 64;    // [s][dh] rows
        const __half* vg = Vt + base + (long)j * 64;         // [dh][s] col slice
        #pragma unroll
        for (int c = tid; c < 512; c += 256) {               // K: 64 rows x 8 chunks
            int r = c >> 3, q = (c & 7) * 8;
            cpa16(smem_u32(ks + r * FA_STR + q), kg + r * 64 + q);
        }
        #pragma unroll
        for (int c = tid; c < 512; c += 256) {               // V: 64 dh-rows x 8 chunks
            int r = c >> 3, q = (c & 7) * 8;
            cpa16(smem_u32(vs + r * FA_STR + q), vg + (long)r * 1024 + q);
        }
        cp_commit();
    };

    loadkv(0);

    // Stage Q tile (128 x 64 halfs, stride FA_STR) in P region; grab fragments.
    {
        const __half* qg = Q + base + (long)qt * 128 * 64;
        #pragma unroll
        for (int c = tid; c < 1024; c += 256) {
            int r = c >> 3, q = (c & 7) * 8;
            *reinterpret_cast<uint4*>(pb + r * FA_STR + q) =
                *reinterpret_cast<const uint4*>(qg + r * 64 + q);
        }
    }
    __syncthreads();
    uint32_t qf[4][4];
    #pragma unroll
    for (int kk = 0; kk < 4; kk++)
        ldsm4(qf[kk][0], qf[kk][1], qf[kk][2], qf[kk][3],
              smem_u32(pb + (w * 16 + arow) * FA_STR + kk * 16 + acol));

    float m0 = -1e30f, m1 = -1e30f, l0 = 0.0f, l1 = 0.0f;
    float oacc[8][4] = {};
    __half* pw = pb + w * FA_PWARP;

    for (int j = 0; j < 16; j++) {
        if (j + 1 < 16) { loadkv(j + 1); cp_wait<1>(); }
        else            { cp_wait<0>(); }
        __syncthreads();   // stage j ready; also protects P/Q region reuse

        const __half* ks = kv + (j & 1) * FA_STAGE;
        const __half* vs = ks + FA_KSZ;

        // S = Q K^T (16 q-rows x 64 s-cols per warp)
        float sacc[8][4];
        #pragma unroll
        for (int ni = 0; ni < 8; ni++)
            #pragma unroll
            for (int q = 0; q < 4; q++) sacc[ni][q] = 0.0f;
        #pragma unroll
        for (int kk = 0; kk < 4; kk++) {
            #pragma unroll
            for (int ni = 0; ni < 8; ni += 2) {
                uint32_t b00, b01, b10, b11;
                ldsm4(b00, b01, b10, b11,
                      smem_u32(ks + (ni * 8 + brow) * FA_STR + kk * 16 + bcol));
                uint32_t bf0[2] = {b00, b01}, bf1[2] = {b10, b11};
                mma16(sacc[ni], qf[kk], bf0);
                mma16(sacc[ni + 1], qf[kk], bf1);
            }
        }

        // online softmax over this 64-col block
        float mx0 = -1e30f, mx1 = -1e30f;
        #pragma unroll
        for (int ni = 0; ni < 8; ni++) {
            mx0 = fmaxf(mx0, fmaxf(sacc[ni][0], sacc[ni][1]));
            mx1 = fmaxf(mx1, fmaxf(sacc[ni][2], sacc[ni][3]));
        }
        mx0 = fmaxf(mx0, __shfl_xor_sync(0xFFFFFFFFu, mx0, 1));
        mx0 = fmaxf(mx0, __shfl_xor_sync(0xFFFFFFFFu, mx0, 2));
        mx1 = fmaxf(mx1, __shfl_xor_sync(0xFFFFFFFFu, mx1, 1));
        mx1 = fmaxf(mx1, __shfl_xor_sync(0xFFFFFFFFu, mx1, 2));
        const float mn0 = fmaxf(m0, mx0), mn1 = fmaxf(m1, mx1);
        const float al0 = __expf(m0 - mn0), al1 = __expf(m1 - mn1);

        float rs0 = 0.0f, rs1 = 0.0f;
        #pragma unroll
        for (int ni = 0; ni < 8; ni++) {
            float p0 = __expf(sacc[ni][0] - mn0);
            float p1 = __expf(sacc[ni][1] - mn0);
            float p2 = __expf(sacc[ni][2] - mn1);
            float p3 = __expf(sacc[ni][3] - mn1);
            rs0 += p0 + p1; rs1 += p2 + p3;
            const int col = ni * 8 + 2 * lc;
            *reinterpret_cast<__half2*>(pw + lr * FA_STR + col)       = __floats2half2_rn(p0, p1);
            *reinterpret_cast<__half2*>(pw + (lr + 8) * FA_STR + col) = __floats2half2_rn(p2, p3);
        }
        rs0 += __shfl_xor_sync(0xFFFFFFFFu, rs0, 1);
        rs0 += __shfl_xor_sync(0xFFFFFFFFu, rs0, 2);
        rs1 += __shfl_xor_sync(0xFFFFFFFFu, rs1, 1);
        rs1 += __shfl_xor_sync(0xFFFFFFFFu, rs1, 2);
        m0 = mn0; m1 = mn1;
        l0 = l0 * al0 + rs0;
        l1 = l1 * al1 + rs1;
        #pragma unroll
        for (int ni = 0; ni < 8; ni++) {
            oacc[ni][0] *= al0; oacc[ni][1] *= al0;
            oacc[ni][2] *= al1; oacc[ni][3] *= al1;
        }
        __syncwarp();

        // O += P V : P (16 x 64) A-operand; Vt smem [dh][s-slice] = B [n][k]
        #pragma unroll
        for (int kk2 = 0; kk2 < 4; kk2++) {
            uint32_t af[4];
            ldsm4(af[0], af[1], af[2], af[3],
                  smem_u32(pw + arow * FA_STR + kk2 * 16 + acol));
            #pragma unroll
            for (int ni = 0; ni < 8; ni += 2) {
                uint32_t b00, b01, b10, b11;
                ldsm4(b00, b01, b10, b11,
                      smem_u32(vs + (ni * 8 + brow) * FA_STR + kk2 * 16 + bcol));
                uint32_t bf0[2] = {b00, b01}, bf1[2] = {b10, b11};
                mma16(oacc[ni], af, bf0);
                mma16(oacc[ni + 1], af, bf1);
            }
        }
        __syncthreads();  // before next loadkv overwrites a stage
    }

    // epilogue: divide by l, write [B,S,D] half
    const float inv0 = 1.0f / l0, inv1 = 1.0f / l1;
    const int b = bh >> 3, h = bh & 7;
    const int r0 = qt * 128 + w * 16 + lr;
    #pragma unroll
    for (int ni = 0; ni < 8; ni++) {
        const int n = h * 64 + ni * 8 + 2 * lc;
        long o0 = ((long)(b * S_ + r0)) * D_ + n;
        long o1 = ((long)(b * S_ + r0 + 8)) * D_ + n;
        *reinterpret_cast<__half2*>(O + o0) = __floats2half2_rn(oacc[ni][0] * inv0, oacc[ni][1] * inv0);
        *reinterpret_cast<__half2*>(O + o1) = __floats2half2_rn(oacc[ni][2] * inv1, oacc[ni][3] * inv1);
    }
}

// ---------------------------------------------------------------------------
// Merged weight prep: transpose + fp16 convert all six weights in one launch.
// ---------------------------------------------------------------------------
__global__ __launch_bounds__(256) void prep_all(
    const float* __restrict__ wq, const float* __restrict__ wk,
    const float* __restrict__ wv, const float* __restrict__ wo,
    const float* __restrict__ w1, const float* __restrict__ w2,
    __half* __restrict__ out)
{
    __shared__ float t[32][33];
    const int id = blockIdx.x;
    const float* src; __half* dst; int K, N, ki, ni;
    if (id < 8192) {
        const int wsel = id >> 11, rem = id & 2047;
        const int layer = rem >> 8, tile = rem & 255;
        K = 512; N = 512; ki = tile >> 4; ni = tile & 15;
        src = (wsel == 0 ? wq : wsel == 1 ? wk : wsel == 2 ? wv : wo) + (long)layer * 262144;
        dst = out + (wsel < 3 ? OFF_TQKV + (long)layer * SZ_QKV + (long)wsel * 262144
                              : OFF_TO + (long)layer * SZ_O);
    } else if (id < 16384) {
        const int rem = id - 8192, layer = rem >> 10, tile = rem & 1023;
        K = 512; N = 2048; ki = tile >> 6; ni = tile & 63;
        src = w1 + (long)layer * 1048576;
        dst = out + OFF_T1 + (long)layer * SZ_1;
    } else {
        const int rem = id - 16384, layer = rem >> 10, tile = rem & 1023;
        K = 2048; N = 512; ki = tile >> 4; ni = tile & 15;
        src = w2 + (long)layer * 1048576;
        dst = out + OFF_T2 + (long)layer * SZ_2;
    }
    const int k0 = ki * 32, n0 = ni * 32;
    #pragma unroll
    for (int i = threadIdx.y; i < 32; i += 8)
        t[i][threadIdx.x] = src[(long)(k0 + i) * N + n0 + threadIdx.x];
    __syncthreads();
    #pragma unroll
    for (int i = threadIdx.y; i < 32; i += 8)
        dst[(long)(n0 + i) * K + k0 + threadIdx.x] = __float2half_rn(t[threadIdx.x][i]);
}

// copy x -> gx (fp32) and gxh (half)
__global__ __launch_bounds__(256) void copy_half(const float* __restrict__ x,
                                                 float* __restrict__ gx,
                                                 __half* __restrict__ gxh, int n4)
{
    int i = blockIdx.x * blockDim.x + threadIdx.x;
    int stride = gridDim.x * blockDim.x;
    for (; i < n4; i += stride) {
        float4 v = reinterpret_cast<const float4*>(x)[i];
        reinterpret_cast<float4*>(gx)[i] = v;
        reinterpret_cast<__half2*>(gxh)[2 * i]     = __floats2half2_rn(v.x, v.y);
        reinterpret_cast<__half2*>(gxh)[2 * i + 1] = __floats2half2_rn(v.z, v.w);
    }
}

// ---------------------------------------------------------------------------
// Row LayerNorm over 512 elements; fp32 out + half out_h.
// ---------------------------------------------------------------------------
__global__ __launch_bounds__(128) void ln_k(const float* __restrict__ in,
                                            const float* __restrict__ g,
                                            const float* __restrict__ be,
                                            float* __restrict__ out,
                                            __half* __restrict__ out_h)
{
    const int row = blockIdx.x;
    const int t = threadIdx.x;
    const float4 v = reinterpret_cast<const float4*>(in + (long)row * D_)[t];

    float s  = v.x + v.y + v.z + v.w;
    float sq = v.x * v.x + v.y * v.y + v.z * v.z + v.w * v.w;
    #pragma unroll
    for (int o = 16; o; o >>= 1) {
        s  += __shfl_xor_sync(0xFFFFFFFFu, s, o);
        sq += __shfl_xor_sync(0xFFFFFFFFu, sq, o);
    }
    __shared__ float sh0[4], sh1[4];
    if ((t & 31) == 0) { sh0[t >> 5] = s; sh1[t >> 5] = sq; }
    __syncthreads();
    s  = sh0[0] + sh0[1] + sh0[2] + sh0[3];
    sq = sh1[0] + sh1[1] + sh1[2] + sh1[3];

    const float mean = s * (1.0f / D_);
    const float var  = sq * (1.0f / D_) - mean * mean;
    const float inv  = rsqrtf(var + LN_EPS);

    const float4 gg = reinterpret_cast<const float4*>(g)[t];
    const float4 bb = reinterpret_cast<const float4*>(be)[t];
    float4 o4;
    o4.x = (v.x - mean) * inv * gg.x + bb.x;
    o4.y = (v.y - mean) * inv * gg.y + bb.y;
    o4.z = (v.z - mean) * inv * gg.z + bb.z;
    o4.w = (v.w - mean) * inv * gg.w + bb.w;
    reinterpret_cast<float4*>(out + (long)row * D_)[t] = o4;
    __half2* oh = reinterpret_cast<__half2*>(out_h + (long)row * D_);
    oh[2 * t]     = __floats2half2_rn(o4.x, o4.y);
    oh[2 * t + 1] = __floats2half2_rn(o4.z, o4.w);
}

// ---------------------------------------------------------------------------
// Host driver
// ---------------------------------------------------------------------------
extern "C" void kernel_launch(void* const* d_in, const int* in_sizes, int n_in,
                              void* d_out, int out_size)
{
    const float* x   = (const float*)d_in[0];
    const float* wq  = (const float*)d_in[1];
    const float* bq  = (const float*)d_in[2];
    const float* wk  = (const float*)d_in[3];
    const float* bk  = (const float*)d_in[4];
    const float* wv  = (const float*)d_in[5];
    const float* bv  = (const float*)d_in[6];
    const float* wo  = (const float*)d_in[7];
    const float* bo  = (const float*)d_in[8];
    const float* g1  = (const float*)d_in[9];
    const float* be1 = (const float*)d_in[10];
    const float* w1  = (const float*)d_in[11];
    const float* b1  = (const float*)d_in[12];
    const float* w2  = (const float*)d_in[13];
    const float* b2  = (const float*)d_in[14];
    const float* g2  = (const float*)d_in[15];
    const float* be2 = (const float*)d_in[16];

    float *gx, *gtmp;
    __half *gxh, *gqkv, *gattn, *gffn, *gwH;
    cudaGetSymbolAddress((void**)&gx,    g_x);
    cudaGetSymbolAddress((void**)&gxh,   g_xh);
    cudaGetSymbolAddress((void**)&gqkv,  g_qkv);
    cudaGetSymbolAddress((void**)&gattn, g_attn);
    cudaGetSymbolAddress((void**)&gtmp,  g_tmp);
    cudaGetSymbolAddress((void**)&gffn,  g_ffn);
    cudaGetSymbolAddress((void**)&gwH,   g_wH);

    constexpr int SM_BIG = smem_bytes<128, 128>();   // 61440
    constexpr int SM_SML = smem_bytes<128, 64>();    // 46080
    (void)cudaFuncSetAttribute(mma_gemm<128,128,M_QKV>,  cudaFuncAttributeMaxDynamicSharedMemorySize, SM_BIG);
    (void)cudaFuncSetAttribute(mma_gemm<128,64,M_RES>,   cudaFuncAttributeMaxDynamicSharedMemorySize, SM_SML);
    (void)cudaFuncSetAttribute(mma_gemm<128,128,M_GELU>, cudaFuncAttributeMaxDynamicSharedMemorySize, SM_BIG);
    (void)cudaFuncSetAttribute(flash_k, cudaFuncAttributeMaxDynamicSharedMemorySize, FA_SMEM);

    copy_half<<<512, 256>>>(x, gx, gxh, M_ROWS * D_ / 4);
    prep_all<<<24576, dim3(32, 8)>>>(wq, wk, wv, wo, w1, w2, gwH);

    const __half* gq  = gqkv;
    const __half* gk  = gqkv + MD;
    const __half* gvT = gqkv + 2 * MD;

    const dim3 gQKV(1536 / 128, M_ROWS / 128);   // (12, 32)
    const dim3 gOP(512 / 64, M_ROWS / 128);      // (8, 32) = 256 CTAs
    const dim3 gF1(2048 / 128, M_ROWS / 128);    // (16, 32)
    const dim3 gFA(S_ / 128, B_ * H_);           // (8, 32)

    for (int l = 0; l < L_; l++) {
        const __half* wqkvH_l = gwH + OFF_TQKV + (long)l * SZ_QKV;
        const __half* woH_l   = gwH + OFF_TO   + (long)l * SZ_O;
        const __half* w1H_l   = gwH + OFF_T1   + (long)l * SZ_1;
        const __half* w2H_l   = gwH + OFF_T2   + (long)l * SZ_2;
        const float* bq_l = bq + (long)l * D_;
        const float* bk_l = bk + (long)l * D_;
        const float* bv_l = bv + (long)l * D_;
        const float* bo_l = bo + (long)l * D_;
        const float* b1_l = b1 + (long)l * F_;
        const float* b2_l = b2 + (long)l * D_;
        const float* g1_l = g1 + (long)l * D_;
        const float* g2_l = g2 + (long)l * D_;
        const float* be1_l = be1 + (long)l * D_;
        const float* be2_l = be2 + (long)l * D_;

        // fused QKV projection -> q,k [B,H,S,DH], vT [B,H,DH,S] (half)
        mma_gemm<128,128,M_QKV><<<gQKV, 256, SM_BIG>>>(
            gxh, wqkvH_l, bq_l, bk_l, bv_l, nullptr, nullptr, gqkv, 1536, 512);

        // fused attention
        flash_k<<<gFA, 256, FA_SMEM>>>(gq, gk, gvT, gattn);

        // O projection + bias + residual (fp32 out), BN=64 for full-wave fill
        mma_gemm<128,64,M_RES><<<gOP, 256, SM_SML>>>(
            gattn, woH_l, bo_l, nullptr, nullptr, gx, gtmp, nullptr, 512, 512);
        ln_k<<<M_ROWS, 128>>>(gtmp, g1_l, be1_l, gx, gxh);

        // FFN1 + GELU (half out)
        mma_gemm<128,128,M_GELU><<<gF1, 256, SM_BIG>>>(
            gxh, w1H_l, b1_l, nullptr, nullptr, nullptr, nullptr, gffn, 2048, 512);
        // FFN2 + bias + residual (fp32 out), BN=64
        mma_gemm<128,64,M_RES><<<gOP, 256, SM_SML>>>(
            gffn, w2H_l, b2_l, nullptr, nullptr, gx, gtmp, nullptr, 512, 2048);
        ln_k<<<M_ROWS, 128>>>(gtmp, g2_l, be2_l,
                              (l == L_ - 1) ? (float*)d_out : gx, gxh);
    }
}

// round 14
// speedup vs baseline: 1.1623x; 1.0186x over previous
#include <cuda_runtime.h>
#include <cuda_fp16.h>
#include <math.h>
#include <stdint.h>
#include <string.h>

// Problem constants
static constexpr int B_ = 4, S_ = 1024, D_ = 512, H_ = 8, F_ = 2048, DH_ = 64, L_ = 8;
static constexpr int M_ROWS = B_ * S_;           // 4096
static constexpr float QK_SCALE = 0.125f;        // 1/sqrt(64)
static constexpr float LN_EPS = 1e-5f;

static constexpr long MD = (long)M_ROWS * D_;    // 2097152
// transposed half weight slabs: [N,K] row-major per layer
static constexpr long SZ_QKV = 1536L * 512, SZ_O = 512L * 512, SZ_1 = 2048L * 512, SZ_2 = 512L * 2048;
static constexpr long OFF_TQKV = 0, OFF_TO = 8 * SZ_QKV, OFF_T1 = OFF_TO + 8 * SZ_O, OFF_T2 = OFF_T1 + 8 * SZ_1;

// Scratch (device globals; no allocation anywhere)
__device__ float g_x[M_ROWS * D_];                          // exact fp32 residual stream
__device__ __align__(16) __half g_xh[M_ROWS * D_];          // half copy for GEMM A
__device__ __align__(16) __half g_qkv[3 * M_ROWS * D_];     // q,k [B,H,S,DH]; vT [B,H,DH,S]
__device__ __align__(16) __half g_attn[M_ROWS * D_];
__device__ float g_tmp[M_ROWS * D_];
__device__ __align__(16) __half g_ffn[M_ROWS * F_];
__device__ __align__(16) __half g_wH[8 * (SZ_QKV + SZ_O + SZ_1 + SZ_2)];   // ~50 MB

enum { M_RES = 2, M_GELU = 3, M_QKV = 6 };

// ---------------------------------------------------------------------------
// helpers
// ---------------------------------------------------------------------------
__device__ __forceinline__ void cpa16(uint32_t smem, const void* gptr) {
    asm volatile("cp.async.cg.shared.global [%0], [%1], 16;\n" :: "r"(smem), "l"(gptr));
}
__device__ __forceinline__ void cp_commit() {
    asm volatile("cp.async.commit_group;\n" ::);
}
template <int N>
__device__ __forceinline__ void cp_wait() {
    asm volatile("cp.async.wait_group %0;\n" :: "n"(N));
}
__device__ __forceinline__ uint32_t smem_u32(const void* p) {
    return (uint32_t)__cvta_generic_to_shared(p);
}
__device__ __forceinline__ uint32_t h2_bits(__half2 h) {
    uint32_t u;
    memcpy(&u, &h, 4);
    return u;
}

__device__ __forceinline__ void ldsm4(uint32_t& r0, uint32_t& r1, uint32_t& r2,
                                      uint32_t& r3, uint32_t addr) {
    asm volatile("ldmatrix.sync.aligned.m8n8.x4.shared.b16 {%0,%1,%2,%3}, [%4];"
                 : "=r"(r0), "=r"(r1), "=r"(r2), "=r"(r3) : "r"(addr));
}

// m16n8k16 f16 mma, fp32 accumulate
__device__ __forceinline__ void mma16(float* c, const uint32_t* a, const uint32_t* b) {
    asm("mma.sync.aligned.m16n8k16.row.col.f32.f16.f16.f32 "
        "{%0,%1,%2,%3}, {%4,%5,%6,%7}, {%8,%9}, {%0,%1,%2,%3};"
        : "+f"(c[0]), "+f"(c[1]), "+f"(c[2]), "+f"(c[3])
        : "r"(a[0]), "r"(a[1]), "r"(a[2]), "r"(a[3]), "r"(b[0]), "r"(b[1]));
}

// ---------------------------------------------------------------------------
// fp16 mma GEMM: 256 threads, 8 warps (4 m-rows x 2 n-cols), warp tile
// 32 x (BN/2). BK=32, 3-stage cp.async. C[m,n] = A[m,k] * Bt[n,k]^T
// ---------------------------------------------------------------------------
static constexpr int G_ASTR = 40;  // halfs per row (32 + 8 pad)
template <int BM, int BN>
static constexpr int smem_bytes() { return 3 * (BM + BN) * G_ASTR * 2; }

template <int BM, int BN, int MODE>
__global__ __launch_bounds__(256, 2)
void mma_gemm(const __half* __restrict__ A, const __half* __restrict__ Bm,
              const float* __restrict__ b0, const float* __restrict__ b1,
              const float* __restrict__ b2, const float* __restrict__ res,
              float* __restrict__ Cf, __half* __restrict__ Ch, int N, int K)
{
    constexpr int BK = 32;
    constexpr int WM = BM / 4, WN = BN / 2;      // 32 x (64|32)
    constexpr int MI = WM / 16, NI = WN / 8;     // 2, (8|4)
    constexpr int ASZ = BM * G_ASTR;
    constexpr int BSZ = BN * G_ASTR;

    extern __shared__ __align__(16) __half smh[];
    __half* As = smh;
    __half* Bs = smh + 3 * ASZ;

    const int bm = blockIdx.y * BM;
    const int bn = blockIdx.x * BN;
    const int tid = threadIdx.x;
    const int lane = tid & 31;
    const int warp = tid >> 5;                   // 0..7
    const int wm0 = (warp & 3) * WM;
    const int wn0 = (warp >> 2) * WN;
    const int lr = lane >> 2;
    const int lc = lane & 3;
    const int arow = lane & 15, acol = (lane >> 4) << 3;
    const int brow = ((lane >> 4) << 3) + (lane & 7);
    const int bcol = ((lane >> 3) & 1) << 3;

    float acc[MI][NI][4];
    #pragma unroll
    for (int i = 0; i < MI; i++)
        #pragma unroll
        for (int j = 0; j < NI; j++)
            #pragma unroll
            for (int q = 0; q < 4; q++) acc[i][j][q] = 0.0f;

    auto load_stage = [&](int j) {
        const int st = j % 3;
        __half* as = As + st * ASZ;
        #pragma unroll
        for (int c = tid; c < BM * 4; c += 256) {
            int r = c >> 2, q = (c & 3) * 8;
            cpa16(smem_u32(as + r * G_ASTR + q), A + (long)(bm + r) * K + j * BK + q);
        }
        __half* bs = Bs + st * BSZ;
        #pragma unroll
        for (int c = tid; c < BN * 4; c += 256) {
            int r = c >> 2, q = (c & 3) * 8;
            cpa16(smem_u32(bs + r * G_ASTR + q), Bm + (long)(bn + r) * K + j * BK + q);
        }
        cp_commit();
    };

    const int NIT = K / BK;
    load_stage(0);
    if (NIT > 1) load_stage(1);

    for (int it = 0; it < NIT; it++) {
        if (it + 2 < NIT) { load_stage(it + 2); cp_wait<2>(); }
        else if (it + 2 == NIT) { cp_wait<1>(); }
        else { cp_wait<0>(); }
        __syncthreads();

        const int st = it % 3;
        const __half* as = As + st * ASZ;
        const __half* bs = Bs + st * BSZ;
        #pragma unroll
        for (int kk = 0; kk < BK; kk += 16) {
            uint32_t af[MI][4];
            #pragma unroll
            for (int mi = 0; mi < MI; mi++)
                ldsm4(af[mi][0], af[mi][1], af[mi][2], af[mi][3],
                      smem_u32(as + (wm0 + mi * 16 + arow) * G_ASTR + kk + acol));
            uint32_t bf[NI][2];
            #pragma unroll
            for (int ni = 0; ni < NI; ni += 2)
                ldsm4(bf[ni][0], bf[ni][1], bf[ni + 1][0], bf[ni + 1][1],
                      smem_u32(bs + (wn0 + ni * 8 + brow) * G_ASTR + kk + bcol));
            #pragma unroll
            for (int mi = 0; mi < MI; mi++)
                #pragma unroll
                for (int ni = 0; ni < NI; ni++)
                    mma16(acc[mi][ni], af[mi], bf[ni]);
        }
        __syncthreads();
    }

    #pragma unroll
    for (int mi = 0; mi < MI; mi++) {
        #pragma unroll
        for (int ni = 0; ni < NI; ni++) {
            #pragma unroll
            for (int ri = 0; ri < 2; ri++) {
                const int m = bm + wm0 + mi * 16 + lr + ri * 8;
                const int n = bn + wn0 + ni * 8 + lc * 2;
                float v0 = acc[mi][ni][ri * 2 + 0];
                float v1 = acc[mi][ni][ri * 2 + 1];
                if (MODE == M_RES) {
                    long o = (long)m * N + n;
                    Cf[o]     = v0 + b0[n]     + res[o];
                    Cf[o + 1] = v1 + b0[n + 1] + res[o + 1];
                } else if (MODE == M_GELU) {
                    v0 += b0[n]; v1 += b0[n + 1];
                    float g0 = 0.5f * v0 * (1.0f + erff(v0 * 0.70710678118654752f));
                    float g1 = 0.5f * v1 * (1.0f + erff(v1 * 0.70710678118654752f));
                    *reinterpret_cast<__half2*>(Ch + (long)m * N + n) = __floats2half2_rn(g0, g1);
                } else { // M_QKV
                    const int t = n >> 9;
                    const int colD = n & 511;
                    const float* bb = (t == 0) ? b0 : ((t == 1) ? b1 : b2);
                    const int b = m >> 10, s = m & 1023, h = colD >> 6, dh0 = colD & 63;
                    const int bh = (b << 3) + h;
                    float u0 = v0 + bb[colD], u1 = v1 + bb[colD + 1];
                    if (t == 0) { u0 *= QK_SCALE; u1 *= QK_SCALE; }
                    if (t == 2) {
                        long o = 2 * MD + ((long)bh << 16) + ((long)dh0 << 10) + s;
                        Ch[o]        = __float2half_rn(u0);
                        Ch[o + 1024] = __float2half_rn(u1);
                    } else {
                        long o = (long)t * MD + (((long)bh * S_ + s) << 6) + dh0;
                        *reinterpret_cast<__half2*>(Ch + o) = __floats2half2_rn(u0, u1);
                    }
                }
            }
        }
    }
}

// ---------------------------------------------------------------------------
// Flash attention: q-tile 128 (8 warps x 16 rows), KV j-tiles of 64 rows,
// 16 iterations, double-buffered, 2 CTAs/SM. P kept in REGISTERS:
// C-frag of S tiles {2k,2k+1} == A-frag of PV k-step k (m16n8k16 identity).
// Q,K: [B,H,S,DH] half (Q pre-scaled). Vt: [B,H,DH,S] half.
// ---------------------------------------------------------------------------
static constexpr int FA_STR = 72;                     // halfs (64 + 8 pad)
static constexpr int FA_KSZ = 64 * FA_STR;            // 4608 halfs per K tile
static constexpr int FA_VSZ = 64 * FA_STR;            // 4608 halfs per V tile
static constexpr int FA_STAGE = FA_KSZ + FA_VSZ;      // 9216 halfs
static constexpr int FA_QSZ = 128 * FA_STR;           // 9216 halfs (Q staging)
static constexpr int FA_SMEM = (2 * FA_STAGE + FA_QSZ) * 2;  // 55296 B

__global__ __launch_bounds__(256, 2)
void flash_k(const __half* __restrict__ Q, const __half* __restrict__ Kt,
             const __half* __restrict__ Vt, __half* __restrict__ O)
{
    extern __shared__ __align__(16) __half smh[];
    __half* kv = smh;
    __half* pb = smh + 2 * FA_STAGE;    // Q staging only

    const int bh = blockIdx.y;
    const int qt = blockIdx.x;
    const int tid = threadIdx.x, lane = tid & 31, w = tid >> 5;
    const int lr = lane >> 2, lc = lane & 3;
    const int arow = lane & 15, acol = (lane >> 4) << 3;
    const int brow = ((lane >> 4) << 3) + (lane & 7);
    const int bcol = ((lane >> 3) & 1) << 3;
    const long base = (long)bh * S_ * DH_;

    auto loadkv = [&](int j) {               // j in [0,16): 64 s-rows
        __half* ks = kv + (j & 1) * FA_STAGE;
        __half* vs = ks + FA_KSZ;
        const __half* kg = Kt + base + (long)j * 64 * 64;    // [s][dh] rows
        const __half* vg = Vt + base + (long)j * 64;         // [dh][s] col slice
        #pragma unroll
        for (int c = tid; c < 512; c += 256) {               // K: 64 rows x 8 chunks
            int r = c >> 3, q = (c & 7) * 8;
            cpa16(smem_u32(ks + r * FA_STR + q), kg + r * 64 + q);
        }
        #pragma unroll
        for (int c = tid; c < 512; c += 256) {               // V: 64 dh-rows x 8 chunks
            int r = c >> 3, q = (c & 7) * 8;
            cpa16(smem_u32(vs + r * FA_STR + q), vg + (long)r * 1024 + q);
        }
        cp_commit();
    };

    loadkv(0);

    // Stage Q tile (128 x 64 halfs, stride FA_STR); grab fragments.
    {
        const __half* qg = Q + base + (long)qt * 128 * 64;
        #pragma unroll
        for (int c = tid; c < 1024; c += 256) {
            int r = c >> 3, q = (c & 7) * 8;
            *reinterpret_cast<uint4*>(pb + r * FA_STR + q) =
                *reinterpret_cast<const uint4*>(qg + r * 64 + q);
        }
    }
    __syncthreads();
    uint32_t qf[4][4];
    #pragma unroll
    for (int kk = 0; kk < 4; kk++)
        ldsm4(qf[kk][0], qf[kk][1], qf[kk][2], qf[kk][3],
              smem_u32(pb + (w * 16 + arow) * FA_STR + kk * 16 + acol));

    float m0 = -1e30f, m1 = -1e30f, l0 = 0.0f, l1 = 0.0f;
    float oacc[8][4] = {};

    for (int j = 0; j < 16; j++) {
        if (j + 1 < 16) { loadkv(j + 1); cp_wait<1>(); }
        else            { cp_wait<0>(); }
        __syncthreads();   // stage j ready

        const __half* ks = kv + (j & 1) * FA_STAGE;
        const __half* vs = ks + FA_KSZ;

        // S = Q K^T (16 q-rows x 64 s-cols per warp)
        float sacc[8][4];
        #pragma unroll
        for (int ni = 0; ni < 8; ni++)
            #pragma unroll
            for (int q = 0; q < 4; q++) sacc[ni][q] = 0.0f;
        #pragma unroll
        for (int kk = 0; kk < 4; kk++) {
            #pragma unroll
            for (int ni = 0; ni < 8; ni += 2) {
                uint32_t b00, b01, b10, b11;
                ldsm4(b00, b01, b10, b11,
                      smem_u32(ks + (ni * 8 + brow) * FA_STR + kk * 16 + bcol));
                uint32_t bf0[2] = {b00, b01}, bf1[2] = {b10, b11};
                mma16(sacc[ni], qf[kk], bf0);
                mma16(sacc[ni + 1], qf[kk], bf1);
            }
        }

        // online softmax over this 64-col block; pack P into A-frag registers
        float mx0 = -1e30f, mx1 = -1e30f;
        #pragma unroll
        for (int ni = 0; ni < 8; ni++) {
            mx0 = fmaxf(mx0, fmaxf(sacc[ni][0], sacc[ni][1]));
            mx1 = fmaxf(mx1, fmaxf(sacc[ni][2], sacc[ni][3]));
        }
        mx0 = fmaxf(mx0, __shfl_xor_sync(0xFFFFFFFFu, mx0, 1));
        mx0 = fmaxf(mx0, __shfl_xor_sync(0xFFFFFFFFu, mx0, 2));
        mx1 = fmaxf(mx1, __shfl_xor_sync(0xFFFFFFFFu, mx1, 1));
        mx1 = fmaxf(mx1, __shfl_xor_sync(0xFFFFFFFFu, mx1, 2));
        const float mn0 = fmaxf(m0, mx0), mn1 = fmaxf(m1, mx1);
        const float al0 = __expf(m0 - mn0), al1 = __expf(m1 - mn1);

        uint32_t pf[8][2];   // pf[ni][0]=half2(p0,p1) rows lr; [1]=half2(p2,p3) rows lr+8
        float rs0 = 0.0f, rs1 = 0.0f;
        #pragma unroll
        for (int ni = 0; ni < 8; ni++) {
            float p0 = __expf(sacc[ni][0] - mn0);
            float p1 = __expf(sacc[ni][1] - mn0);
            float p2 = __expf(sacc[ni][2] - mn1);
            float p3 = __expf(sacc[ni][3] - mn1);
            rs0 += p0 + p1; rs1 += p2 + p3;
            pf[ni][0] = h2_bits(__floats2half2_rn(p0, p1));
            pf[ni][1] = h2_bits(__floats2half2_rn(p2, p3));
        }
        rs0 += __shfl_xor_sync(0xFFFFFFFFu, rs0, 1);
        rs0 += __shfl_xor_sync(0xFFFFFFFFu, rs0, 2);
        rs1 += __shfl_xor_sync(0xFFFFFFFFu, rs1, 1);
        rs1 += __shfl_xor_sync(0xFFFFFFFFu, rs1, 2);
        m0 = mn0; m1 = mn1;
        l0 = l0 * al0 + rs0;
        l1 = l1 * al1 + rs1;
        #pragma unroll
        for (int ni = 0; ni < 8; ni++) {
            oacc[ni][0] *= al0; oacc[ni][1] *= al0;
            oacc[ni][2] *= al1; oacc[ni][3] *= al1;
        }

        // O += P V : P A-frag = {pf[2k][0], pf[2k][1], pf[2k+1][0], pf[2k+1][1]}
        #pragma unroll
        for (int kk2 = 0; kk2 < 4; kk2++) {
            uint32_t af[4] = { pf[2 * kk2][0], pf[2 * kk2][1],
                               pf[2 * kk2 + 1][0], pf[2 * kk2 + 1][1] };
            #pragma unroll
            for (int ni = 0; ni < 8; ni += 2) {
                uint32_t b00, b01, b10, b11;
                ldsm4(b00, b01, b10, b11,
                      smem_u32(vs + (ni * 8 + brow) * FA_STR + kk2 * 16 + bcol));
                uint32_t bf0[2] = {b00, b01}, bf1[2] = {b10, b11};
                mma16(oacc[ni], af, bf0);
                mma16(oacc[ni + 1], af, bf1);
            }
        }
        __syncthreads();  // before next loadkv overwrites a stage
    }

    // epilogue: divide by l, write [B,S,D] half
    const float inv0 = 1.0f / l0, inv1 = 1.0f / l1;
    const int b = bh >> 3, h = bh & 7;
    const int r0 = qt * 128 + w * 16 + lr;
    #pragma unroll
    for (int ni = 0; ni < 8; ni++) {
        const int n = h * 64 + ni * 8 + 2 * lc;
        long o0 = ((long)(b * S_ + r0)) * D_ + n;
        long o1 = ((long)(b * S_ + r0 + 8)) * D_ + n;
        *reinterpret_cast<__half2*>(O + o0) = __floats2half2_rn(oacc[ni][0] * inv0, oacc[ni][1] * inv0);
        *reinterpret_cast<__half2*>(O + o1) = __floats2half2_rn(oacc[ni][2] * inv1, oacc[ni][3] * inv1);
    }
}

// ---------------------------------------------------------------------------
// Merged weight prep: transpose + fp16 convert all six weights in one launch.
// ---------------------------------------------------------------------------
__global__ __launch_bounds__(256) void prep_all(
    const float* __restrict__ wq, const float* __restrict__ wk,
    const float* __restrict__ wv, const float* __restrict__ wo,
    const float* __restrict__ w1, const float* __restrict__ w2,
    __half* __restrict__ out)
{
    __shared__ float t[32][33];
    const int id = blockIdx.x;
    const float* src; __half* dst; int K, N, ki, ni;
    if (id < 8192) {
        const int wsel = id >> 11, rem = id & 2047;
        const int layer = rem >> 8, tile = rem & 255;
        K = 512; N = 512; ki = tile >> 4; ni = tile & 15;
        src = (wsel == 0 ? wq : wsel == 1 ? wk : wsel == 2 ? wv : wo) + (long)layer * 262144;
        dst = out + (wsel < 3 ? OFF_TQKV + (long)layer * SZ_QKV + (long)wsel * 262144
                              : OFF_TO + (long)layer * SZ_O);
    } else if (id < 16384) {
        const int rem = id - 8192, layer = rem >> 10, tile = rem & 1023;
        K = 512; N = 2048; ki = tile >> 6; ni = tile & 63;
        src = w1 + (long)layer * 1048576;
        dst = out + OFF_T1 + (long)layer * SZ_1;
    } else {
        const int rem = id - 16384, layer = rem >> 10, tile = rem & 1023;
        K = 2048; N = 512; ki = tile >> 4; ni = tile & 15;
        src = w2 + (long)layer * 1048576;
        dst = out + OFF_T2 + (long)layer * SZ_2;
    }
    const int k0 = ki * 32, n0 = ni * 32;
    #pragma unroll
    for (int i = threadIdx.y; i < 32; i += 8)
        t[i][threadIdx.x] = src[(long)(k0 + i) * N + n0 + threadIdx.x];
    __syncthreads();
    #pragma unroll
    for (int i = threadIdx.y; i < 32; i += 8)
        dst[(long)(n0 + i) * K + k0 + threadIdx.x] = __float2half_rn(t[threadIdx.x][i]);
}

// copy x -> gx (fp32) and gxh (half)
__global__ __launch_bounds__(256) void copy_half(const float* __restrict__ x,
                                                 float* __restrict__ gx,
                                                 __half* __restrict__ gxh, int n4)
{
    int i = blockIdx.x * blockDim.x + threadIdx.x;
    int stride = gridDim.x * blockDim.x;
    for (; i < n4; i += stride) {
        float4 v = reinterpret_cast<const float4*>(x)[i];
        reinterpret_cast<float4*>(gx)[i] = v;
        reinterpret_cast<__half2*>(gxh)[2 * i]     = __floats2half2_rn(v.x, v.y);
        reinterpret_cast<__half2*>(gxh)[2 * i + 1] = __floats2half2_rn(v.z, v.w);
    }
}

// ---------------------------------------------------------------------------
// Row LayerNorm over 512 elements; fp32 out + half out_h.
// ---------------------------------------------------------------------------
__global__ __launch_bounds__(128) void ln_k(const float* __restrict__ in,
                                            const float* __restrict__ g,
                                            const float* __restrict__ be,
                                            float* __restrict__ out,
                                            __half* __restrict__ out_h)
{
    const int row = blockIdx.x;
    const int t = threadIdx.x;
    const float4 v = reinterpret_cast<const float4*>(in + (long)row * D_)[t];

    float s  = v.x + v.y + v.z + v.w;
    float sq = v.x * v.x + v.y * v.y + v.z * v.z + v.w * v.w;
    #pragma unroll
    for (int o = 16; o; o >>= 1) {
        s  += __shfl_xor_sync(0xFFFFFFFFu, s, o);
        sq += __shfl_xor_sync(0xFFFFFFFFu, sq, o);
    }
    __shared__ float sh0[4], sh1[4];
    if ((t & 31) == 0) { sh0[t >> 5] = s; sh1[t >> 5] = sq; }
    __syncthreads();
    s  = sh0[0] + sh0[1] + sh0[2] + sh0[3];
    sq = sh1[0] + sh1[1] + sh1[2] + sh1[3];

    const float mean = s * (1.0f / D_);
    const float var  = sq * (1.0f / D_) - mean * mean;
    const float inv  = rsqrtf(var + LN_EPS);

    const float4 gg = reinterpret_cast<const float4*>(g)[t];
    const float4 bb = reinterpret_cast<const float4*>(be)[t];
    float4 o4;
    o4.x = (v.x - mean) * inv * gg.x + bb.x;
    o4.y = (v.y - mean) * inv * gg.y + bb.y;
    o4.z = (v.z - mean) * inv * gg.z + bb.z;
    o4.w = (v.w - mean) * inv * gg.w + bb.w;
    reinterpret_cast<float4*>(out + (long)row * D_)[t] = o4;
    __half2* oh = reinterpret_cast<__half2*>(out_h + (long)row * D_);
    oh[2 * t]     = __floats2half2_rn(o4.x, o4.y);
    oh[2 * t + 1] = __floats2half2_rn(o4.z, o4.w);
}

// ---------------------------------------------------------------------------
// Host driver
// ---------------------------------------------------------------------------
extern "C" void kernel_launch(void* const* d_in, const int* in_sizes, int n_in,
                              void* d_out, int out_size)
{
    const float* x   = (const float*)d_in[0];
    const float* wq  = (const float*)d_in[1];
    const float* bq  = (const float*)d_in[2];
    const float* wk  = (const float*)d_in[3];
    const float* bk  = (const float*)d_in[4];
    const float* wv  = (const float*)d_in[5];
    const float* bv  = (const float*)d_in[6];
    const float* wo  = (const float*)d_in[7];
    const float* bo  = (const float*)d_in[8];
    const float* g1  = (const float*)d_in[9];
    const float* be1 = (const float*)d_in[10];
    const float* w1  = (const float*)d_in[11];
    const float* b1  = (const float*)d_in[12];
    const float* w2  = (const float*)d_in[13];
    const float* b2  = (const float*)d_in[14];
    const float* g2  = (const float*)d_in[15];
    const float* be2 = (const float*)d_in[16];

    float *gx, *gtmp;
    __half *gxh, *gqkv, *gattn, *gffn, *gwH;
    cudaGetSymbolAddress((void**)&gx,    g_x);
    cudaGetSymbolAddress((void**)&gxh,   g_xh);
    cudaGetSymbolAddress((void**)&gqkv,  g_qkv);
    cudaGetSymbolAddress((void**)&gattn, g_attn);
    cudaGetSymbolAddress((void**)&gtmp,  g_tmp);
    cudaGetSymbolAddress((void**)&gffn,  g_ffn);
    cudaGetSymbolAddress((void**)&gwH,   g_wH);

    constexpr int SM_BIG = smem_bytes<128, 128>();   // 61440
    constexpr int SM_SML = smem_bytes<128, 64>();    // 46080
    (void)cudaFuncSetAttribute(mma_gemm<128,128,M_QKV>,  cudaFuncAttributeMaxDynamicSharedMemorySize, SM_BIG);
    (void)cudaFuncSetAttribute(mma_gemm<128,64,M_RES>,   cudaFuncAttributeMaxDynamicSharedMemorySize, SM_SML);
    (void)cudaFuncSetAttribute(mma_gemm<128,128,M_GELU>, cudaFuncAttributeMaxDynamicSharedMemorySize, SM_BIG);
    (void)cudaFuncSetAttribute(flash_k, cudaFuncAttributeMaxDynamicSharedMemorySize, FA_SMEM);

    copy_half<<<512, 256>>>(x, gx, gxh, M_ROWS * D_ / 4);
    prep_all<<<24576, dim3(32, 8)>>>(wq, wk, wv, wo, w1, w2, gwH);

    const __half* gq  = gqkv;
    const __half* gk  = gqkv + MD;
    const __half* gvT = gqkv + 2 * MD;

    const dim3 gQKV(1536 / 128, M_ROWS / 128);   // (12, 32)
    const dim3 gOP(512 / 64, M_ROWS / 128);      // (8, 32) = 256 CTAs
    const dim3 gF1(2048 / 128, M_ROWS / 128);    // (16, 32)
    const dim3 gFA(S_ / 128, B_ * H_);           // (8, 32)

    for (int l = 0; l < L_; l++) {
        const __half* wqkvH_l = gwH + OFF_TQKV + (long)l * SZ_QKV;
        const __half* woH_l   = gwH + OFF_TO   + (long)l * SZ_O;
        const __half* w1H_l   = gwH + OFF_T1   + (long)l * SZ_1;
        const __half* w2H_l   = gwH + OFF_T2   + (long)l * SZ_2;
        const float* bq_l = bq + (long)l * D_;
        const float* bk_l = bk + (long)l * D_;
        const float* bv_l = bv + (long)l * D_;
        const float* bo_l = bo + (long)l * D_;
        const float* b1_l = b1 + (long)l * F_;
        const float* b2_l = b2 + (long)l * D_;
        const float* g1_l = g1 + (long)l * D_;
        const float* g2_l = g2 + (long)l * D_;
        const float* be1_l = be1 + (long)l * D_;
        const float* be2_l = be2 + (long)l * D_;

        // fused QKV projection -> q,k [B,H,S,DH], vT [B,H,DH,S] (half)
        mma_gemm<128,128,M_QKV><<<gQKV, 256, SM_BIG>>>(
            gxh, wqkvH_l, bq_l, bk_l, bv_l, nullptr, nullptr, gqkv, 1536, 512);

        // fused attention (register-resident P)
        flash_k<<<gFA, 256, FA_SMEM>>>(gq, gk, gvT, gattn);

        // O projection + bias + residual (fp32 out), BN=64 for full-wave fill
        mma_gemm<128,64,M_RES><<<gOP, 256, SM_SML>>>(
            gattn, woH_l, bo_l, nullptr, nullptr, gx, gtmp, nullptr, 512, 512);
        ln_k<<<M_ROWS, 128>>>(gtmp, g1_l, be1_l, gx, gxh);

        // FFN1 + GELU (half out)
        mma_gemm<128,128,M_GELU><<<gF1, 256, SM_BIG>>>(
            gxh, w1H_l, b1_l, nullptr, nullptr, nullptr, nullptr, gffn, 2048, 512);
        // FFN2 + bias + residual (fp32 out), BN=64
        mma_gemm<128,64,M_RES><<<gOP, 256, SM_SML>>>(
            gffn, w2H_l, b2_l, nullptr, nullptr, gx, gtmp, nullptr, 512, 2048);
        ln_k<<<M_ROWS, 128>>>(gtmp, g2_l, be2_l,
                              (l == L_ - 1) ? (float*)d_out : gx, gxh);
    }
}

// round 15
// speedup vs baseline: 1.2927x; 1.1121x over previous
#include <cuda_runtime.h>
#include <cuda_fp16.h>
#include <math.h>
#include <stdint.h>
#include <string.h>

// Problem constants
static constexpr int B_ = 4, S_ = 1024, D_ = 512, H_ = 8, F_ = 2048, DH_ = 64, L_ = 8;
static constexpr int M_ROWS = B_ * S_;           // 4096
static constexpr float QK_SCALE = 0.125f;        // 1/sqrt(64)
static constexpr float LN_EPS = 1e-5f;

static constexpr long MD = (long)M_ROWS * D_;    // 2097152
// transposed half weight slabs: [N,K] row-major per layer
static constexpr long SZ_QKV = 1536L * 512, SZ_O = 512L * 512, SZ_1 = 2048L * 512, SZ_2 = 512L * 2048;
static constexpr long OFF_TQKV = 0, OFF_TO = 8 * SZ_QKV, OFF_T1 = OFF_TO + 8 * SZ_O, OFF_T2 = OFF_T1 + 8 * SZ_1;

// Scratch (device globals; no allocation anywhere)
__device__ float g_x[M_ROWS * D_];                          // exact fp32 residual stream
__device__ __align__(16) __half g_xh[M_ROWS * D_];          // half copy for GEMM A
__device__ __align__(16) __half g_qkv[3 * M_ROWS * D_];     // q,k [B,H,S,DH]; vT [B,H,DH,S]
__device__ __align__(16) __half g_attn[M_ROWS * D_];
__device__ float g_tmp[M_ROWS * D_];
__device__ __align__(16) __half g_ffn[M_ROWS * F_];
__device__ __align__(16) __half g_wH[8 * (SZ_QKV + SZ_O + SZ_1 + SZ_2)];   // ~50 MB

enum { M_RES = 2, M_GELU = 3, M_QKV = 6 };

// ---------------------------------------------------------------------------
// helpers
// ---------------------------------------------------------------------------
__device__ __forceinline__ void cpa16(uint32_t smem, const void* gptr) {
    asm volatile("cp.async.cg.shared.global [%0], [%1], 16;\n" :: "r"(smem), "l"(gptr));
}
__device__ __forceinline__ void cp_commit() {
    asm volatile("cp.async.commit_group;\n" ::);
}
template <int N>
__device__ __forceinline__ void cp_wait() {
    asm volatile("cp.async.wait_group %0;\n" :: "n"(N));
}
__device__ __forceinline__ uint32_t smem_u32(const void* p) {
    return (uint32_t)__cvta_generic_to_shared(p);
}
__device__ __forceinline__ uint32_t h2_bits(__half2 h) {
    uint32_t u;
    memcpy(&u, &h, 4);
    return u;
}

__device__ __forceinline__ void ldsm4(uint32_t& r0, uint32_t& r1, uint32_t& r2,
                                      uint32_t& r3, uint32_t addr) {
    asm volatile("ldmatrix.sync.aligned.m8n8.x4.shared.b16 {%0,%1,%2,%3}, [%4];"
                 : "=r"(r0), "=r"(r1), "=r"(r2), "=r"(r3) : "r"(addr));
}

// m16n8k16 f16 mma, fp32 accumulate
__device__ __forceinline__ void mma16(float* c, const uint32_t* a, const uint32_t* b) {
    asm("mma.sync.aligned.m16n8k16.row.col.f32.f16.f16.f32 "
        "{%0,%1,%2,%3}, {%4,%5,%6,%7}, {%8,%9}, {%0,%1,%2,%3};"
        : "+f"(c[0]), "+f"(c[1]), "+f"(c[2]), "+f"(c[3])
        : "r"(a[0]), "r"(a[1]), "r"(a[2]), "r"(a[3]), "r"(b[0]), "r"(b[1]));
}

// ---------------------------------------------------------------------------
// fp16 mma GEMM: 256 threads, 8 warps (4 m-rows x 2 n-cols), warp tile
// 32 x (BN/2). BK=64, 2-stage cp.async. C[m,n] = A[m,k] * Bt[n,k]^T
// ---------------------------------------------------------------------------
static constexpr int G_BK = 64;
static constexpr int G_ASTR = G_BK + 8;  // 72 halfs per row
template <int BM, int BN>
static constexpr int smem_bytes() { return 2 * (BM + BN) * G_ASTR * 2; }

template <int BM, int BN, int MODE>
__global__ __launch_bounds__(256, 2)
void mma_gemm(const __half* __restrict__ A, const __half* __restrict__ Bm,
              const float* __restrict__ b0, const float* __restrict__ b1,
              const float* __restrict__ b2, const float* __restrict__ res,
              float* __restrict__ Cf, __half* __restrict__ Ch, int N, int K)
{
    constexpr int WM = BM / 4, WN = BN / 2;      // 32 x (64|32)
    constexpr int MI = WM / 16, NI = WN / 8;     // 2, (8|4)
    constexpr int ASZ = BM * G_ASTR;
    constexpr int BSZ = BN * G_ASTR;

    extern __shared__ __align__(16) __half smh[];
    __half* As = smh;
    __half* Bs = smh + 2 * ASZ;

    const int bm = blockIdx.y * BM;
    const int bn = blockIdx.x * BN;
    const int tid = threadIdx.x;
    const int lane = tid & 31;
    const int warp = tid >> 5;                   // 0..7
    const int wm0 = (warp & 3) * WM;
    const int wn0 = (warp >> 2) * WN;
    const int lr = lane >> 2;
    const int lc = lane & 3;
    const int arow = lane & 15, acol = (lane >> 4) << 3;
    const int brow = ((lane >> 4) << 3) + (lane & 7);
    const int bcol = ((lane >> 3) & 1) << 3;

    float acc[MI][NI][4];
    #pragma unroll
    for (int i = 0; i < MI; i++)
        #pragma unroll
        for (int j = 0; j < NI; j++)
            #pragma unroll
            for (int q = 0; q < 4; q++) acc[i][j][q] = 0.0f;

    auto load_stage = [&](int j) {
        const int st = j & 1;
        __half* as = As + st * ASZ;
        #pragma unroll
        for (int c = tid; c < BM * 8; c += 256) {
            int r = c >> 3, q = (c & 7) * 8;
            cpa16(smem_u32(as + r * G_ASTR + q), A + (long)(bm + r) * K + j * G_BK + q);
        }
        __half* bs = Bs + st * BSZ;
        #pragma unroll
        for (int c = tid; c < BN * 8; c += 256) {
            int r = c >> 3, q = (c & 7) * 8;
            cpa16(smem_u32(bs + r * G_ASTR + q), Bm + (long)(bn + r) * K + j * G_BK + q);
        }
        cp_commit();
    };

    const int NIT = K / G_BK;
    load_stage(0);

    for (int it = 0; it < NIT; it++) {
        if (it + 1 < NIT) { load_stage(it + 1); cp_wait<1>(); }
        else              { cp_wait<0>(); }
        __syncthreads();

        const int st = it & 1;
        const __half* as = As + st * ASZ;
        const __half* bs = Bs + st * BSZ;
        #pragma unroll
        for (int kk = 0; kk < G_BK; kk += 16) {
            uint32_t af[MI][4];
            #pragma unroll
            for (int mi = 0; mi < MI; mi++)
                ldsm4(af[mi][0], af[mi][1], af[mi][2], af[mi][3],
                      smem_u32(as + (wm0 + mi * 16 + arow) * G_ASTR + kk + acol));
            uint32_t bf[NI][2];
            #pragma unroll
            for (int ni = 0; ni < NI; ni += 2)
                ldsm4(bf[ni][0], bf[ni][1], bf[ni + 1][0], bf[ni + 1][1],
                      smem_u32(bs + (wn0 + ni * 8 + brow) * G_ASTR + kk + bcol));
            #pragma unroll
            for (int mi = 0; mi < MI; mi++)
                #pragma unroll
                for (int ni = 0; ni < NI; ni++)
                    mma16(acc[mi][ni], af[mi], bf[ni]);
        }
        __syncthreads();
    }

    #pragma unroll
    for (int mi = 0; mi < MI; mi++) {
        #pragma unroll
        for (int ni = 0; ni < NI; ni++) {
            #pragma unroll
            for (int ri = 0; ri < 2; ri++) {
                const int m = bm + wm0 + mi * 16 + lr + ri * 8;
                const int n = bn + wn0 + ni * 8 + lc * 2;
                float v0 = acc[mi][ni][ri * 2 + 0];
                float v1 = acc[mi][ni][ri * 2 + 1];
                if (MODE == M_RES) {
                    long o = (long)m * N + n;
                    Cf[o]     = v0 + b0[n]     + res[o];
                    Cf[o + 1] = v1 + b0[n + 1] + res[o + 1];
                } else if (MODE == M_GELU) {
                    v0 += b0[n]; v1 += b0[n + 1];
                    float g0 = 0.5f * v0 * (1.0f + erff(v0 * 0.70710678118654752f));
                    float g1 = 0.5f * v1 * (1.0f + erff(v1 * 0.70710678118654752f));
                    *reinterpret_cast<__half2*>(Ch + (long)m * N + n) = __floats2half2_rn(g0, g1);
                } else { // M_QKV
                    const int t = n >> 9;
                    const int colD = n & 511;
                    const float* bb = (t == 0) ? b0 : ((t == 1) ? b1 : b2);
                    const int b = m >> 10, s = m & 1023, h = colD >> 6, dh0 = colD & 63;
                    const int bh = (b << 3) + h;
                    float u0 = v0 + bb[colD], u1 = v1 + bb[colD + 1];
                    if (t == 0) { u0 *= QK_SCALE; u1 *= QK_SCALE; }
                    if (t == 2) {
                        long o = 2 * MD + ((long)bh << 16) + ((long)dh0 << 10) + s;
                        Ch[o]        = __float2half_rn(u0);
                        Ch[o + 1024] = __float2half_rn(u1);
                    } else {
                        long o = (long)t * MD + (((long)bh * S_ + s) << 6) + dh0;
                        *reinterpret_cast<__half2*>(Ch + o) = __floats2half2_rn(u0, u1);
                    }
                }
            }
        }
    }
}

// ---------------------------------------------------------------------------
// Flash attention: q-tile 128 (8 warps x 16 rows), KV j-tiles of 64 rows,
// 16 iterations, double-buffered, 2 CTAs/SM. P kept in REGISTERS:
// C-frag of S tiles {2k,2k+1} == A-frag of PV k-step k (m16n8k16 identity).
// Q,K: [B,H,S,DH] half (Q pre-scaled). Vt: [B,H,DH,S] half.
// ---------------------------------------------------------------------------
static constexpr int FA_STR = 72;                     // halfs (64 + 8 pad)
static constexpr int FA_KSZ = 64 * FA_STR;            // 4608 halfs per K tile
static constexpr int FA_VSZ = 64 * FA_STR;            // 4608 halfs per V tile
static constexpr int FA_STAGE = FA_KSZ + FA_VSZ;      // 9216 halfs
static constexpr int FA_QSZ = 128 * FA_STR;           // 9216 halfs (Q staging)
static constexpr int FA_SMEM = (2 * FA_STAGE + FA_QSZ) * 2;  // 55296 B

__global__ __launch_bounds__(256, 2)
void flash_k(const __half* __restrict__ Q, const __half* __restrict__ Kt,
             const __half* __restrict__ Vt, __half* __restrict__ O)
{
    extern __shared__ __align__(16) __half smh[];
    __half* kv = smh;
    __half* pb = smh + 2 * FA_STAGE;    // Q staging only

    const int bh = blockIdx.y;
    const int qt = blockIdx.x;
    const int tid = threadIdx.x, lane = tid & 31, w = tid >> 5;
    const int lr = lane >> 2, lc = lane & 3;
    const int arow = lane & 15, acol = (lane >> 4) << 3;
    const int brow = ((lane >> 4) << 3) + (lane & 7);
    const int bcol = ((lane >> 3) & 1) << 3;
    const long base = (long)bh * S_ * DH_;

    auto loadkv = [&](int j) {               // j in [0,16): 64 s-rows
        __half* ks = kv + (j & 1) * FA_STAGE;
        __half* vs = ks + FA_KSZ;
        const __half* kg = Kt + base + (long)j * 64 * 64;    // [s][dh] rows
        const __half* vg = Vt + base + (long)j * 64;         // [dh][s] col slice
        #pragma unroll
        for (int c = tid; c < 512; c += 256) {               // K: 64 rows x 8 chunks
            int r = c >> 3, q = (c & 7) * 8;
            cpa16(smem_u32(ks + r * FA_STR + q), kg + r * 64 + q);
        }
        #pragma unroll
        for (int c = tid; c < 512; c += 256) {               // V: 64 dh-rows x 8 chunks
            int r = c >> 3, q = (c & 7) * 8;
            cpa16(smem_u32(vs + r * FA_STR + q), vg + (long)r * 1024 + q);
        }
        cp_commit();
    };

    loadkv(0);

    // Stage Q tile (128 x 64 halfs, stride FA_STR); grab fragments.
    {
        const __half* qg = Q + base + (long)qt * 128 * 64;
        #pragma unroll
        for (int c = tid; c < 1024; c += 256) {
            int r = c >> 3, q = (c & 7) * 8;
            *reinterpret_cast<uint4*>(pb + r * FA_STR + q) =
                *reinterpret_cast<const uint4*>(qg + r * 64 + q);
        }
    }
    __syncthreads();
    uint32_t qf[4][4];
    #pragma unroll
    for (int kk = 0; kk < 4; kk++)
        ldsm4(qf[kk][0], qf[kk][1], qf[kk][2], qf[kk][3],
              smem_u32(pb + (w * 16 + arow) * FA_STR + kk * 16 + acol));

    float m0 = -1e30f, m1 = -1e30f, l0 = 0.0f, l1 = 0.0f;
    float oacc[8][4] = {};

    for (int j = 0; j < 16; j++) {
        if (j + 1 < 16) { loadkv(j + 1); cp_wait<1>(); }
        else            { cp_wait<0>(); }
        __syncthreads();   // stage j ready

        const __half* ks = kv + (j & 1) * FA_STAGE;
        const __half* vs = ks + FA_KSZ;

        // S = Q K^T (16 q-rows x 64 s-cols per warp)
        float sacc[8][4];
        #pragma unroll
        for (int ni = 0; ni < 8; ni++)
            #pragma unroll
            for (int q = 0; q < 4; q++) sacc[ni][q] = 0.0f;
        #pragma unroll
        for (int kk = 0; kk < 4; kk++) {
            #pragma unroll
            for (int ni = 0; ni < 8; ni += 2) {
                uint32_t b00, b01, b10, b11;
                ldsm4(b00, b01, b10, b11,
                      smem_u32(ks + (ni * 8 + brow) * FA_STR + kk * 16 + bcol));
                uint32_t bf0[2] = {b00, b01}, bf1[2] = {b10, b11};
                mma16(sacc[ni], qf[kk], bf0);
                mma16(sacc[ni + 1], qf[kk], bf1);
            }
        }

        // online softmax over this 64-col block; pack P into A-frag registers
        float mx0 = -1e30f, mx1 = -1e30f;
        #pragma unroll
        for (int ni = 0; ni < 8; ni++) {
            mx0 = fmaxf(mx0, fmaxf(sacc[ni][0], sacc[ni][1]));
            mx1 = fmaxf(mx1, fmaxf(sacc[ni][2], sacc[ni][3]));
        }
        mx0 = fmaxf(mx0, __shfl_xor_sync(0xFFFFFFFFu, mx0, 1));
        mx0 = fmaxf(mx0, __shfl_xor_sync(0xFFFFFFFFu, mx0, 2));
        mx1 = fmaxf(mx1, __shfl_xor_sync(0xFFFFFFFFu, mx1, 1));
        mx1 = fmaxf(mx1, __shfl_xor_sync(0xFFFFFFFFu, mx1, 2));
        const float mn0 = fmaxf(m0, mx0), mn1 = fmaxf(m1, mx1);
        const float al0 = __expf(m0 - mn0), al1 = __expf(m1 - mn1);

        uint32_t pf[8][2];   // pf[ni][0]=half2(p0,p1) rows lr; [1]=half2(p2,p3) rows lr+8
        float rs0 = 0.0f, rs1 = 0.0f;
        #pragma unroll
        for (int ni = 0; ni < 8; ni++) {
            float p0 = __expf(sacc[ni][0] - mn0);
            float p1 = __expf(sacc[ni][1] - mn0);
            float p2 = __expf(sacc[ni][2] - mn1);
            float p3 = __expf(sacc[ni][3] - mn1);
            rs0 += p0 + p1; rs1 += p2 + p3;
            pf[ni][0] = h2_bits(__floats2half2_rn(p0, p1));
            pf[ni][1] = h2_bits(__floats2half2_rn(p2, p3));
        }
        rs0 += __shfl_xor_sync(0xFFFFFFFFu, rs0, 1);
        rs0 += __shfl_xor_sync(0xFFFFFFFFu, rs0, 2);
        rs1 += __shfl_xor_sync(0xFFFFFFFFu, rs1, 1);
        rs1 += __shfl_xor_sync(0xFFFFFFFFu, rs1, 2);
        m0 = mn0; m1 = mn1;
        l0 = l0 * al0 + rs0;
        l1 = l1 * al1 + rs1;
        #pragma unroll
        for (int ni = 0; ni < 8; ni++) {
            oacc[ni][0] *= al0; oacc[ni][1] *= al0;
            oacc[ni][2] *= al1; oacc[ni][3] *= al1;
        }

        // O += P V : P A-frag = {pf[2k][0], pf[2k][1], pf[2k+1][0], pf[2k+1][1]}
        #pragma unroll
        for (int kk2 = 0; kk2 < 4; kk2++) {
            uint32_t af[4] = { pf[2 * kk2][0], pf[2 * kk2][1],
                               pf[2 * kk2 + 1][0], pf[2 * kk2 + 1][1] };
            #pragma unroll
            for (int ni = 0; ni < 8; ni += 2) {
                uint32_t b00, b01, b10, b11;
                ldsm4(b00, b01, b10, b11,
                      smem_u32(vs + (ni * 8 + brow) * FA_STR + kk2 * 16 + bcol));
                uint32_t bf0[2] = {b00, b01}, bf1[2] = {b10, b11};
                mma16(oacc[ni], af, bf0);
                mma16(oacc[ni + 1], af, bf1);
            }
        }
        __syncthreads();  // before next loadkv overwrites a stage
    }

    // epilogue: divide by l, write [B,S,D] half
    const float inv0 = 1.0f / l0, inv1 = 1.0f / l1;
    const int b = bh >> 3, h = bh & 7;
    const int r0 = qt * 128 + w * 16 + lr;
    #pragma unroll
    for (int ni = 0; ni < 8; ni++) {
        const int n = h * 64 + ni * 8 + 2 * lc;
        long o0 = ((long)(b * S_ + r0)) * D_ + n;
        long o1 = ((long)(b * S_ + r0 + 8)) * D_ + n;
        *reinterpret_cast<__half2*>(O + o0) = __floats2half2_rn(oacc[ni][0] * inv0, oacc[ni][1] * inv0);
        *reinterpret_cast<__half2*>(O + o1) = __floats2half2_rn(oacc[ni][2] * inv1, oacc[ni][3] * inv1);
    }
}

// ---------------------------------------------------------------------------
// Merged weight prep: transpose + fp16 convert all six weights in one launch.
// ---------------------------------------------------------------------------
__global__ __launch_bounds__(256) void prep_all(
    const float* __restrict__ wq, const float* __restrict__ wk,
    const float* __restrict__ wv, const float* __restrict__ wo,
    const float* __restrict__ w1, const float* __restrict__ w2,
    __half* __restrict__ out)
{
    __shared__ float t[32][33];
    const int id = blockIdx.x;
    const float* src; __half* dst; int K, N, ki, ni;
    if (id < 8192) {
        const int wsel = id >> 11, rem = id & 2047;
        const int layer = rem >> 8, tile = rem & 255;
        K = 512; N = 512; ki = tile >> 4; ni = tile & 15;
        src = (wsel == 0 ? wq : wsel == 1 ? wk : wsel == 2 ? wv : wo) + (long)layer * 262144;
        dst = out + (wsel < 3 ? OFF_TQKV + (long)layer * SZ_QKV + (long)wsel * 262144
                              : OFF_TO + (long)layer * SZ_O);
    } else if (id < 16384) {
        const int rem = id - 8192, layer = rem >> 10, tile = rem & 1023;
        K = 512; N = 2048; ki = tile >> 6; ni = tile & 63;
        src = w1 + (long)layer * 1048576;
        dst = out + OFF_T1 + (long)layer * SZ_1;
    } else {
        const int rem = id - 16384, layer = rem >> 10, tile = rem & 1023;
        K = 2048; N = 512; ki = tile >> 4; ni = tile & 15;
        src = w2 + (long)layer * 1048576;
        dst = out + OFF_T2 + (long)layer * SZ_2;
    }
    const int k0 = ki * 32, n0 = ni * 32;
    #pragma unroll
    for (int i = threadIdx.y; i < 32; i += 8)
        t[i][threadIdx.x] = src[(long)(k0 + i) * N + n0 + threadIdx.x];
    __syncthreads();
    #pragma unroll
    for (int i = threadIdx.y; i < 32; i += 8)
        dst[(long)(n0 + i) * K + k0 + threadIdx.x] = __float2half_rn(t[threadIdx.x][i]);
}

// copy x -> gx (fp32) and gxh (half)
__global__ __launch_bounds__(256) void copy_half(const float* __restrict__ x,
                                                 float* __restrict__ gx,
                                                 __half* __restrict__ gxh, int n4)
{
    int i = blockIdx.x * blockDim.x + threadIdx.x;
    int stride = gridDim.x * blockDim.x;
    for (; i < n4; i += stride) {
        float4 v = reinterpret_cast<const float4*>(x)[i];
        reinterpret_cast<float4*>(gx)[i] = v;
        reinterpret_cast<__half2*>(gxh)[2 * i]     = __floats2half2_rn(v.x, v.y);
        reinterpret_cast<__half2*>(gxh)[2 * i + 1] = __floats2half2_rn(v.z, v.w);
    }
}

// ---------------------------------------------------------------------------
// Row LayerNorm over 512 elements; one WARP per row, 8 rows per 256-thr CTA.
// Warp-only reductions (no smem, no __syncthreads).
// ---------------------------------------------------------------------------
__global__ __launch_bounds__(256) void ln_k(const float* __restrict__ in,
                                            const float* __restrict__ g,
                                            const float* __restrict__ be,
                                            float* __restrict__ out,
                                            __half* __restrict__ out_h)
{
    const int lane = threadIdx.x & 31;
    const int row = blockIdx.x * 8 + (threadIdx.x >> 5);
    const float4* ip = reinterpret_cast<const float4*>(in + (long)row * D_);

    float4 v[4];
    float s = 0.0f, sq = 0.0f;
    #pragma unroll
    for (int i = 0; i < 4; i++) {
        v[i] = ip[lane + 32 * i];
        s  += v[i].x + v[i].y + v[i].z + v[i].w;
        sq += v[i].x * v[i].x + v[i].y * v[i].y + v[i].z * v[i].z + v[i].w * v[i].w;
    }
    #pragma unroll
    for (int o = 16; o; o >>= 1) {
        s  += __shfl_xor_sync(0xFFFFFFFFu, s, o);
        sq += __shfl_xor_sync(0xFFFFFFFFu, sq, o);
    }

    const float mean = s * (1.0f / D_);
    const float var  = sq * (1.0f / D_) - mean * mean;
    const float inv  = rsqrtf(var + LN_EPS);

    float4* op = reinterpret_cast<float4*>(out + (long)row * D_);
    __half2* oh = reinterpret_cast<__half2*>(out_h + (long)row * D_);
    #pragma unroll
    for (int i = 0; i < 4; i++) {
        const int j = lane + 32 * i;
        const float4 gg = reinterpret_cast<const float4*>(g)[j];
        const float4 bb = reinterpret_cast<const float4*>(be)[j];
        float4 o4;
        o4.x = (v[i].x - mean) * inv * gg.x + bb.x;
        o4.y = (v[i].y - mean) * inv * gg.y + bb.y;
        o4.z = (v[i].z - mean) * inv * gg.z + bb.z;
        o4.w = (v[i].w - mean) * inv * gg.w + bb.w;
        op[j] = o4;
        oh[2 * j]     = __floats2half2_rn(o4.x, o4.y);
        oh[2 * j + 1] = __floats2half2_rn(o4.z, o4.w);
    }
}

// ---------------------------------------------------------------------------
// Host driver
// ---------------------------------------------------------------------------
extern "C" void kernel_launch(void* const* d_in, const int* in_sizes, int n_in,
                              void* d_out, int out_size)
{
    const float* x   = (const float*)d_in[0];
    const float* wq  = (const float*)d_in[1];
    const float* bq  = (const float*)d_in[2];
    const float* wk  = (const float*)d_in[3];
    const float* bk  = (const float*)d_in[4];
    const float* wv  = (const float*)d_in[5];
    const float* bv  = (const float*)d_in[6];
    const float* wo  = (const float*)d_in[7];
    const float* bo  = (const float*)d_in[8];
    const float* g1  = (const float*)d_in[9];
    const float* be1 = (const float*)d_in[10];
    const float* w1  = (const float*)d_in[11];
    const float* b1  = (const float*)d_in[12];
    const float* w2  = (const float*)d_in[13];
    const float* b2  = (const float*)d_in[14];
    const float* g2  = (const float*)d_in[15];
    const float* be2 = (const float*)d_in[16];

    float *gx, *gtmp;
    __half *gxh, *gqkv, *gattn, *gffn, *gwH;
    cudaGetSymbolAddress((void**)&gx,    g_x);
    cudaGetSymbolAddress((void**)&gxh,   g_xh);
    cudaGetSymbolAddress((void**)&gqkv,  g_qkv);
    cudaGetSymbolAddress((void**)&gattn, g_attn);
    cudaGetSymbolAddress((void**)&gtmp,  g_tmp);
    cudaGetSymbolAddress((void**)&gffn,  g_ffn);
    cudaGetSymbolAddress((void**)&gwH,   g_wH);

    constexpr int SM_BIG = smem_bytes<128, 128>();   // 73728
    constexpr int SM_SML = smem_bytes<128, 64>();    // 55296
    (void)cudaFuncSetAttribute(mma_gemm<128,128,M_QKV>,  cudaFuncAttributeMaxDynamicSharedMemorySize, SM_BIG);
    (void)cudaFuncSetAttribute(mma_gemm<128,64,M_RES>,   cudaFuncAttributeMaxDynamicSharedMemorySize, SM_SML);
    (void)cudaFuncSetAttribute(mma_gemm<128,128,M_GELU>, cudaFuncAttributeMaxDynamicSharedMemorySize, SM_BIG);
    (void)cudaFuncSetAttribute(flash_k, cudaFuncAttributeMaxDynamicSharedMemorySize, FA_SMEM);

    copy_half<<<512, 256>>>(x, gx, gxh, M_ROWS * D_ / 4);
    prep_all<<<24576, dim3(32, 8)>>>(wq, wk, wv, wo, w1, w2, gwH);

    const __half* gq  = gqkv;
    const __half* gk  = gqkv + MD;
    const __half* gvT = gqkv + 2 * MD;

    const dim3 gQKV(1536 / 128, M_ROWS / 128);   // (12, 32)
    const dim3 gOP(512 / 64, M_ROWS / 128);      // (8, 32) = 256 CTAs
    const dim3 gF1(2048 / 128, M_ROWS / 128);    // (16, 32)
    const dim3 gFA(S_ / 128, B_ * H_);           // (8, 32)

    for (int l = 0; l < L_; l++) {
        const __half* wqkvH_l = gwH + OFF_TQKV + (long)l * SZ_QKV;
        const __half* woH_l   = gwH + OFF_TO   + (long)l * SZ_O;
        const __half* w1H_l   = gwH + OFF_T1   + (long)l * SZ_1;
        const __half* w2H_l   = gwH + OFF_T2   + (long)l * SZ_2;
        const float* bq_l = bq + (long)l * D_;
        const float* bk_l = bk + (long)l * D_;
        const float* bv_l = bv + (long)l * D_;
        const float* bo_l = bo + (long)l * D_;
        const float* b1_l = b1 + (long)l * F_;
        const float* b2_l = b2 + (long)l * D_;
        const float* g1_l = g1 + (long)l * D_;
        const float* g2_l = g2 + (long)l * D_;
        const float* be1_l = be1 + (long)l * D_;
        const float* be2_l = be2 + (long)l * D_;

        // fused QKV projection -> q,k [B,H,S,DH], vT [B,H,DH,S] (half)
        mma_gemm<128,128,M_QKV><<<gQKV, 256, SM_BIG>>>(
            gxh, wqkvH_l, bq_l, bk_l, bv_l, nullptr, nullptr, gqkv, 1536, 512);

        // fused attention (register-resident P)
        flash_k<<<gFA, 256, FA_SMEM>>>(gq, gk, gvT, gattn);

        // O projection + bias + residual (fp32 out), BN=64 for full-wave fill
        mma_gemm<128,64,M_RES><<<gOP, 256, SM_SML>>>(
            gattn, woH_l, bo_l, nullptr, nullptr, gx, gtmp, nullptr, 512, 512);
        ln_k<<<M_ROWS / 8, 256>>>(gtmp, g1_l, be1_l, gx, gxh);

        // FFN1 + GELU (half out)
        mma_gemm<128,128,M_GELU><<<gF1, 256, SM_BIG>>>(
            gxh, w1H_l, b1_l, nullptr, nullptr, nullptr, nullptr, gffn, 2048, 512);
        // FFN2 + bias + residual (fp32 out), BN=64
        mma_gemm<128,64,M_RES><<<gOP, 256, SM_SML>>>(
            gffn, w2H_l, b2_l, nullptr, nullptr, gx, gtmp, nullptr, 512, 2048);
        ln_k<<<M_ROWS / 8, 256>>>(gtmp, g2_l, be2_l,
                                  (l == L_ - 1) ? (float*)d_out : gx, gxh);
    }
}

// round 16
// speedup vs baseline: 1.3425x; 1.0386x over previous
#include <cuda_runtime.h>
#include <cuda_fp16.h>
#include <math.h>
#include <stdint.h>
#include <string.h>

// Problem constants
static constexpr int B_ = 4, S_ = 1024, D_ = 512, H_ = 8, F_ = 2048, DH_ = 64, L_ = 8;
static constexpr int M_ROWS = B_ * S_;           // 4096
static constexpr float QK_SCALE = 0.125f;        // 1/sqrt(64)
static constexpr float LN_EPS = 1e-5f;

static constexpr long MD = (long)M_ROWS * D_;    // 2097152
// transposed half weight slabs: [N,K] row-major per layer
static constexpr long SZ_QKV = 1536L * 512, SZ_O = 512L * 512, SZ_1 = 2048L * 512, SZ_2 = 512L * 2048;
static constexpr long OFF_TQKV = 0, OFF_TO = 8 * SZ_QKV, OFF_T1 = OFF_TO + 8 * SZ_O, OFF_T2 = OFF_T1 + 8 * SZ_1;

// Scratch (device globals; no allocation anywhere)
__device__ float g_x[M_ROWS * D_];                          // exact fp32 residual stream
__device__ __align__(16) __half g_xh[M_ROWS * D_];          // half copy for GEMM A
__device__ __align__(16) __half g_qkv[3 * M_ROWS * D_];     // q,k [B,H,S,DH]; vT [B,H,DH,S]
__device__ __align__(16) __half g_attn[M_ROWS * D_];
__device__ float g_tmp[M_ROWS * D_];
__device__ __align__(16) __half g_ffn[M_ROWS * F_];
__device__ __align__(16) __half g_wH[8 * (SZ_QKV + SZ_O + SZ_1 + SZ_2)];   // ~50 MB

enum { M_RES = 2, M_GELU = 3, M_QKV = 6 };

// ---------------------------------------------------------------------------
// helpers
// ---------------------------------------------------------------------------
__device__ __forceinline__ void cpa16(uint32_t smem, const void* gptr) {
    asm volatile("cp.async.cg.shared.global [%0], [%1], 16;\n" :: "r"(smem), "l"(gptr));
}
__device__ __forceinline__ void cp_commit() {
    asm volatile("cp.async.commit_group;\n" ::);
}
template <int N>
__device__ __forceinline__ void cp_wait() {
    asm volatile("cp.async.wait_group %0;\n" :: "n"(N));
}
__device__ __forceinline__ uint32_t smem_u32(const void* p) {
    return (uint32_t)__cvta_generic_to_shared(p);
}
__device__ __forceinline__ uint32_t h2_bits(__half2 h) {
    uint32_t u;
    memcpy(&u, &h, 4);
    return u;
}

__device__ __forceinline__ void ldsm4(uint32_t& r0, uint32_t& r1, uint32_t& r2,
                                      uint32_t& r3, uint32_t addr) {
    asm volatile("ldmatrix.sync.aligned.m8n8.x4.shared.b16 {%0,%1,%2,%3}, [%4];"
                 : "=r"(r0), "=r"(r1), "=r"(r2), "=r"(r3) : "r"(addr));
}

// m16n8k16 f16 mma, fp32 accumulate
__device__ __forceinline__ void mma16(float* c, const uint32_t* a, const uint32_t* b) {
    asm("mma.sync.aligned.m16n8k16.row.col.f32.f16.f16.f32 "
        "{%0,%1,%2,%3}, {%4,%5,%6,%7}, {%8,%9}, {%0,%1,%2,%3};"
        : "+f"(c[0]), "+f"(c[1]), "+f"(c[2]), "+f"(c[3])
        : "r"(a[0]), "r"(a[1]), "r"(a[2]), "r"(a[3]), "r"(b[0]), "r"(b[1]));
}

// ---------------------------------------------------------------------------
// fp16 mma GEMM: 256 threads, 8 warps (4 m-rows x 2 n-cols), warp tile
// 32 x (BN/2). BK=64. 3 rotating smem buffers, 1-ahead prefetch:
// single barrier per iteration (WAR distance = 2 iterations, covered by
// the previous iteration's barrier).
// ---------------------------------------------------------------------------
static constexpr int G_BK = 64;
static constexpr int G_ASTR = G_BK + 8;  // 72 halfs per row
template <int BM, int BN>
static constexpr int smem_bytes() { return 3 * (BM + BN) * G_ASTR * 2; }

template <int BM, int BN, int MODE>
__global__ __launch_bounds__(256, 2)
void mma_gemm(const __half* __restrict__ A, const __half* __restrict__ Bm,
              const float* __restrict__ b0, const float* __restrict__ b1,
              const float* __restrict__ b2, const float* __restrict__ res,
              float* __restrict__ Cf, __half* __restrict__ Ch, int N, int K)
{
    constexpr int WM = BM / 4, WN = BN / 2;      // 32 x (64|32)
    constexpr int MI = WM / 16, NI = WN / 8;     // 2, (8|4)
    constexpr int ASZ = BM * G_ASTR;
    constexpr int BSZ = BN * G_ASTR;

    extern __shared__ __align__(16) __half smh[];
    __half* As = smh;                 // 3 x ASZ
    __half* Bs = smh + 3 * ASZ;       // 3 x BSZ

    const int bm = blockIdx.y * BM;
    const int bn = blockIdx.x * BN;
    const int tid = threadIdx.x;
    const int lane = tid & 31;
    const int warp = tid >> 5;                   // 0..7
    const int wm0 = (warp & 3) * WM;
    const int wn0 = (warp >> 2) * WN;
    const int lr = lane >> 2;
    const int lc = lane & 3;
    const int arow = lane & 15, acol = (lane >> 4) << 3;
    const int brow = ((lane >> 4) << 3) + (lane & 7);
    const int bcol = ((lane >> 3) & 1) << 3;

    float acc[MI][NI][4];
    #pragma unroll
    for (int i = 0; i < MI; i++)
        #pragma unroll
        for (int j = 0; j < NI; j++)
            #pragma unroll
            for (int q = 0; q < 4; q++) acc[i][j][q] = 0.0f;

    auto load_stage = [&](int j) {
        const int st = j % 3;
        __half* as = As + st * ASZ;
        #pragma unroll
        for (int c = tid; c < BM * 8; c += 256) {
            int r = c >> 3, q = (c & 7) * 8;
            cpa16(smem_u32(as + r * G_ASTR + q), A + (long)(bm + r) * K + j * G_BK + q);
        }
        __half* bs = Bs + st * BSZ;
        #pragma unroll
        for (int c = tid; c < BN * 8; c += 256) {
            int r = c >> 3, q = (c & 7) * 8;
            cpa16(smem_u32(bs + r * G_ASTR + q), Bm + (long)(bn + r) * K + j * G_BK + q);
        }
        cp_commit();
    };

    const int NIT = K / G_BK;
    load_stage(0);

    for (int it = 0; it < NIT; it++) {
        if (it + 1 < NIT) { load_stage(it + 1); cp_wait<1>(); }
        else              { cp_wait<0>(); }
        __syncthreads();   // stage it visible to all; also orders prior reads

        const int st = it % 3;
        const __half* as = As + st * ASZ;
        const __half* bs = Bs + st * BSZ;
        #pragma unroll
        for (int kk = 0; kk < G_BK; kk += 16) {
            uint32_t af[MI][4];
            #pragma unroll
            for (int mi = 0; mi < MI; mi++)
                ldsm4(af[mi][0], af[mi][1], af[mi][2], af[mi][3],
                      smem_u32(as + (wm0 + mi * 16 + arow) * G_ASTR + kk + acol));
            uint32_t bf[NI][2];
            #pragma unroll
            for (int ni = 0; ni < NI; ni += 2)
                ldsm4(bf[ni][0], bf[ni][1], bf[ni + 1][0], bf[ni + 1][1],
                      smem_u32(bs + (wn0 + ni * 8 + brow) * G_ASTR + kk + bcol));
            #pragma unroll
            for (int mi = 0; mi < MI; mi++)
                #pragma unroll
                for (int ni = 0; ni < NI; ni++)
                    mma16(acc[mi][ni], af[mi], bf[ni]);
        }
        // no trailing barrier: next write target is stage (it+2)%3,
        // last read two iterations ago (covered by this iteration's barrier)
    }

    #pragma unroll
    for (int mi = 0; mi < MI; mi++) {
        #pragma unroll
        for (int ni = 0; ni < NI; ni++) {
            #pragma unroll
            for (int ri = 0; ri < 2; ri++) {
                const int m = bm + wm0 + mi * 16 + lr + ri * 8;
                const int n = bn + wn0 + ni * 8 + lc * 2;
                float v0 = acc[mi][ni][ri * 2 + 0];
                float v1 = acc[mi][ni][ri * 2 + 1];
                if (MODE == M_RES) {
                    long o = (long)m * N + n;
                    Cf[o]     = v0 + b0[n]     + res[o];
                    Cf[o + 1] = v1 + b0[n + 1] + res[o + 1];
                } else if (MODE == M_GELU) {
                    v0 += b0[n]; v1 += b0[n + 1];
                    float g0 = 0.5f * v0 * (1.0f + erff(v0 * 0.70710678118654752f));
                    float g1 = 0.5f * v1 * (1.0f + erff(v1 * 0.70710678118654752f));
                    *reinterpret_cast<__half2*>(Ch + (long)m * N + n) = __floats2half2_rn(g0, g1);
                } else { // M_QKV
                    const int t = n >> 9;
                    const int colD = n & 511;
                    const float* bb = (t == 0) ? b0 : ((t == 1) ? b1 : b2);
                    const int b = m >> 10, s = m & 1023, h = colD >> 6, dh0 = colD & 63;
                    const int bh = (b << 3) + h;
                    float u0 = v0 + bb[colD], u1 = v1 + bb[colD + 1];
                    if (t == 0) { u0 *= QK_SCALE; u1 *= QK_SCALE; }
                    if (t == 2) {
                        long o = 2 * MD + ((long)bh << 16) + ((long)dh0 << 10) + s;
                        Ch[o]        = __float2half_rn(u0);
                        Ch[o + 1024] = __float2half_rn(u1);
                    } else {
                        long o = (long)t * MD + (((long)bh * S_ + s) << 6) + dh0;
                        *reinterpret_cast<__half2*>(Ch + o) = __floats2half2_rn(u0, u1);
                    }
                }
            }
        }
    }
}

// ---------------------------------------------------------------------------
// Flash attention: q-tile 128 (8 warps x 16 rows), KV j-tiles of 64 rows,
// 16 iterations. 3 rotating KV buffers, 1-ahead prefetch, single barrier
// per iteration. Register-resident P (C-frag == A-frag identity).
// Q,K: [B,H,S,DH] half (Q pre-scaled). Vt: [B,H,DH,S] half. 2 CTAs/SM.
// ---------------------------------------------------------------------------
static constexpr int FA_STR = 72;                     // halfs (64 + 8 pad)
static constexpr int FA_KSZ = 64 * FA_STR;            // 4608 halfs per K tile
static constexpr int FA_VSZ = 64 * FA_STR;            // 4608 halfs per V tile
static constexpr int FA_STAGE = FA_KSZ + FA_VSZ;      // 9216 halfs
static constexpr int FA_QSZ = 128 * FA_STR;           // 9216 halfs (Q staging)
static constexpr int FA_SMEM = (3 * FA_STAGE + FA_QSZ) * 2;  // 73728 B

__global__ __launch_bounds__(256, 2)
void flash_k(const __half* __restrict__ Q, const __half* __restrict__ Kt,
             const __half* __restrict__ Vt, __half* __restrict__ O)
{
    extern __shared__ __align__(16) __half smh[];
    __half* kv = smh;                    // 3 x FA_STAGE
    __half* pb = smh + 3 * FA_STAGE;     // Q staging only

    const int bh = blockIdx.y;
    const int qt = blockIdx.x;
    const int tid = threadIdx.x, lane = tid & 31, w = tid >> 5;
    const int lr = lane >> 2, lc = lane & 3;
    const int arow = lane & 15, acol = (lane >> 4) << 3;
    const int brow = ((lane >> 4) << 3) + (lane & 7);
    const int bcol = ((lane >> 3) & 1) << 3;
    const long base = (long)bh * S_ * DH_;

    auto loadkv = [&](int j) {               // j in [0,16): 64 s-rows
        __half* ks = kv + (j % 3) * FA_STAGE;
        __half* vs = ks + FA_KSZ;
        const __half* kg = Kt + base + (long)j * 64 * 64;    // [s][dh] rows
        const __half* vg = Vt + base + (long)j * 64;         // [dh][s] col slice
        #pragma unroll
        for (int c = tid; c < 512; c += 256) {               // K: 64 rows x 8 chunks
            int r = c >> 3, q = (c & 7) * 8;
            cpa16(smem_u32(ks + r * FA_STR + q), kg + r * 64 + q);
        }
        #pragma unroll
        for (int c = tid; c < 512; c += 256) {               // V: 64 dh-rows x 8 chunks
            int r = c >> 3, q = (c & 7) * 8;
            cpa16(smem_u32(vs + r * FA_STR + q), vg + (long)r * 1024 + q);
        }
        cp_commit();
    };

    loadkv(0);

    // Stage Q tile (128 x 64 halfs, stride FA_STR); grab fragments.
    {
        const __half* qg = Q + base + (long)qt * 128 * 64;
        #pragma unroll
        for (int c = tid; c < 1024; c += 256) {
            int r = c >> 3, q = (c & 7) * 8;
            *reinterpret_cast<uint4*>(pb + r * FA_STR + q) =
                *reinterpret_cast<const uint4*>(qg + r * 64 + q);
        }
    }
    __syncthreads();
    uint32_t qf[4][4];
    #pragma unroll
    for (int kk = 0; kk < 4; kk++)
        ldsm4(qf[kk][0], qf[kk][1], qf[kk][2], qf[kk][3],
              smem_u32(pb + (w * 16 + arow) * FA_STR + kk * 16 + acol));

    float m0 = -1e30f, m1 = -1e30f, l0 = 0.0f, l1 = 0.0f;
    float oacc[8][4] = {};

    for (int j = 0; j < 16; j++) {
        if (j + 1 < 16) { loadkv(j + 1); cp_wait<1>(); }
        else            { cp_wait<0>(); }
        __syncthreads();   // stage j visible; orders reads 2 iterations back

        const __half* ks = kv + (j % 3) * FA_STAGE;
        const __half* vs = ks + FA_KSZ;

        // S = Q K^T (16 q-rows x 64 s-cols per warp)
        float sacc[8][4];
        #pragma unroll
        for (int ni = 0; ni < 8; ni++)
            #pragma unroll
            for (int q = 0; q < 4; q++) sacc[ni][q] = 0.0f;
        #pragma unroll
        for (int kk = 0; kk < 4; kk++) {
            #pragma unroll
            for (int ni = 0; ni < 8; ni += 2) {
                uint32_t b00, b01, b10, b11;
                ldsm4(b00, b01, b10, b11,
                      smem_u32(ks + (ni * 8 + brow) * FA_STR + kk * 16 + bcol));
                uint32_t bf0[2] = {b00, b01}, bf1[2] = {b10, b11};
                mma16(sacc[ni], qf[kk], bf0);
                mma16(sacc[ni + 1], qf[kk], bf1);
            }
        }

        // online softmax over this 64-col block; pack P into A-frag registers
        float mx0 = -1e30f, mx1 = -1e30f;
        #pragma unroll
        for (int ni = 0; ni < 8; ni++) {
            mx0 = fmaxf(mx0, fmaxf(sacc[ni][0], sacc[ni][1]));
            mx1 = fmaxf(mx1, fmaxf(sacc[ni][2], sacc[ni][3]));
        }
        mx0 = fmaxf(mx0, __shfl_xor_sync(0xFFFFFFFFu, mx0, 1));
        mx0 = fmaxf(mx0, __shfl_xor_sync(0xFFFFFFFFu, mx0, 2));
        mx1 = fmaxf(mx1, __shfl_xor_sync(0xFFFFFFFFu, mx1, 1));
        mx1 = fmaxf(mx1, __shfl_xor_sync(0xFFFFFFFFu, mx1, 2));
        const float mn0 = fmaxf(m0, mx0), mn1 = fmaxf(m1, mx1);
        const float al0 = __expf(m0 - mn0), al1 = __expf(m1 - mn1);

        uint32_t pf[8][2];   // pf[ni][0]=half2(p0,p1) rows lr; [1]=half2(p2,p3) rows lr+8
        float rs0 = 0.0f, rs1 = 0.0f;
        #pragma unroll
        for (int ni = 0; ni < 8; ni++) {
            float p0 = __expf(sacc[ni][0] - mn0);
            float p1 = __expf(sacc[ni][1] - mn0);
            float p2 = __expf(sacc[ni][2] - mn1);
            float p3 = __expf(sacc[ni][3] - mn1);
            rs0 += p0 + p1; rs1 += p2 + p3;
            pf[ni][0] = h2_bits(__floats2half2_rn(p0, p1));
            pf[ni][1] = h2_bits(__floats2half2_rn(p2, p3));
        }
        rs0 += __shfl_xor_sync(0xFFFFFFFFu, rs0, 1);
        rs0 += __shfl_xor_sync(0xFFFFFFFFu, rs0, 2);
        rs1 += __shfl_xor_sync(0xFFFFFFFFu, rs1, 1);
        rs1 += __shfl_xor_sync(0xFFFFFFFFu, rs1, 2);
        m0 = mn0; m1 = mn1;
        l0 = l0 * al0 + rs0;
        l1 = l1 * al1 + rs1;
        #pragma unroll
        for (int ni = 0; ni < 8; ni++) {
            oacc[ni][0] *= al0; oacc[ni][1] *= al0;
            oacc[ni][2] *= al1; oacc[ni][3] *= al1;
        }

        // O += P V : P A-frag = {pf[2k][0], pf[2k][1], pf[2k+1][0], pf[2k+1][1]}
        #pragma unroll
        for (int kk2 = 0; kk2 < 4; kk2++) {
            uint32_t af[4] = { pf[2 * kk2][0], pf[2 * kk2][1],
                               pf[2 * kk2 + 1][0], pf[2 * kk2 + 1][1] };
            #pragma unroll
            for (int ni = 0; ni < 8; ni += 2) {
                uint32_t b00, b01, b10, b11;
                ldsm4(b00, b01, b10, b11,
                      smem_u32(vs + (ni * 8 + brow) * FA_STR + kk2 * 16 + bcol));
                uint32_t bf0[2] = {b00, b01}, bf1[2] = {b10, b11};
                mma16(oacc[ni], af, bf0);
                mma16(oacc[ni + 1], af, bf1);
            }
        }
        // no trailing barrier (3-buffer rotation)
    }

    // epilogue: divide by l, write [B,S,D] half
    const float inv0 = 1.0f / l0, inv1 = 1.0f / l1;
    const int b = bh >> 3, h = bh & 7;
    const int r0 = qt * 128 + w * 16 + lr;
    #pragma unroll
    for (int ni = 0; ni < 8; ni++) {
        const int n = h * 64 + ni * 8 + 2 * lc;
        long o0 = ((long)(b * S_ + r0)) * D_ + n;
        long o1 = ((long)(b * S_ + r0 + 8)) * D_ + n;
        *reinterpret_cast<__half2*>(O + o0) = __floats2half2_rn(oacc[ni][0] * inv0, oacc[ni][1] * inv0);
        *reinterpret_cast<__half2*>(O + o1) = __floats2half2_rn(oacc[ni][2] * inv1, oacc[ni][3] * inv1);
    }
}

// ---------------------------------------------------------------------------
// Merged weight prep: transpose + fp16 convert all six weights in one launch.
// ---------------------------------------------------------------------------
__global__ __launch_bounds__(256) void prep_all(
    const float* __restrict__ wq, const float* __restrict__ wk,
    const float* __restrict__ wv, const float* __restrict__ wo,
    const float* __restrict__ w1, const float* __restrict__ w2,
    __half* __restrict__ out)
{
    __shared__ float t[32][33];
    const int id = blockIdx.x;
    const float* src; __half* dst; int K, N, ki, ni;
    if (id < 8192) {
        const int wsel = id >> 11, rem = id & 2047;
        const int layer = rem >> 8, tile = rem & 255;
        K = 512; N = 512; ki = tile >> 4; ni = tile & 15;
        src = (wsel == 0 ? wq : wsel == 1 ? wk : wsel == 2 ? wv : wo) + (long)layer * 262144;
        dst = out + (wsel < 3 ? OFF_TQKV + (long)layer * SZ_QKV + (long)wsel * 262144
                              : OFF_TO + (long)layer * SZ_O);
    } else if (id < 16384) {
        const int rem = id - 8192, layer = rem >> 10, tile = rem & 1023;
        K = 512; N = 2048; ki = tile >> 6; ni = tile & 63;
        src = w1 + (long)layer * 1048576;
        dst = out + OFF_T1 + (long)layer * SZ_1;
    } else {
        const int rem = id - 16384, layer = rem >> 10, tile = rem & 1023;
        K = 2048; N = 512; ki = tile >> 4; ni = tile & 15;
        src = w2 + (long)layer * 1048576;
        dst = out + OFF_T2 + (long)layer * SZ_2;
    }
    const int k0 = ki * 32, n0 = ni * 32;
    #pragma unroll
    for (int i = threadIdx.y; i < 32; i += 8)
        t[i][threadIdx.x] = src[(long)(k0 + i) * N + n0 + threadIdx.x];
    __syncthreads();
    #pragma unroll
    for (int i = threadIdx.y; i < 32; i += 8)
        dst[(long)(n0 + i) * K + k0 + threadIdx.x] = __float2half_rn(t[threadIdx.x][i]);
}

// copy x -> gx (fp32) and gxh (half)
__global__ __launch_bounds__(256) void copy_half(const float* __restrict__ x,
                                                 float* __restrict__ gx,
                                                 __half* __restrict__ gxh, int n4)
{
    int i = blockIdx.x * blockDim.x + threadIdx.x;
    int stride = gridDim.x * blockDim.x;
    for (; i < n4; i += stride) {
        float4 v = reinterpret_cast<const float4*>(x)[i];
        reinterpret_cast<float4*>(gx)[i] = v;
        reinterpret_cast<__half2*>(gxh)[2 * i]     = __floats2half2_rn(v.x, v.y);
        reinterpret_cast<__half2*>(gxh)[2 * i + 1] = __floats2half2_rn(v.z, v.w);
    }
}

// ---------------------------------------------------------------------------
// Row LayerNorm over 512 elements; one WARP per row, 8 rows per 256-thr CTA.
// ---------------------------------------------------------------------------
__global__ __launch_bounds__(256) void ln_k(const float* __restrict__ in,
                                            const float* __restrict__ g,
                                            const float* __restrict__ be,
                                            float* __restrict__ out,
                                            __half* __restrict__ out_h)
{
    const int lane = threadIdx.x & 31;
    const int row = blockIdx.x * 8 + (threadIdx.x >> 5);
    const float4* ip = reinterpret_cast<const float4*>(in + (long)row * D_);

    float4 v[4];
    float s = 0.0f, sq = 0.0f;
    #pragma unroll
    for (int i = 0; i < 4; i++) {
        v[i] = ip[lane + 32 * i];
        s  += v[i].x + v[i].y + v[i].z + v[i].w;
        sq += v[i].x * v[i].x + v[i].y * v[i].y + v[i].z * v[i].z + v[i].w * v[i].w;
    }
    #pragma unroll
    for (int o = 16; o; o >>= 1) {
        s  += __shfl_xor_sync(0xFFFFFFFFu, s, o);
        sq += __shfl_xor_sync(0xFFFFFFFFu, sq, o);
    }

    const float mean = s * (1.0f / D_);
    const float var  = sq * (1.0f / D_) - mean * mean;
    const float inv  = rsqrtf(var + LN_EPS);

    float4* op = reinterpret_cast<float4*>(out + (long)row * D_);
    __half2* oh = reinterpret_cast<__half2*>(out_h + (long)row * D_);
    #pragma unroll
    for (int i = 0; i < 4; i++) {
        const int j = lane + 32 * i;
        const float4 gg = reinterpret_cast<const float4*>(g)[j];
        const float4 bb = reinterpret_cast<const float4*>(be)[j];
        float4 o4;
        o4.x = (v[i].x - mean) * inv * gg.x + bb.x;
        o4.y = (v[i].y - mean) * inv * gg.y + bb.y;
        o4.z = (v[i].z - mean) * inv * gg.z + bb.z;
        o4.w = (v[i].w - mean) * inv * gg.w + bb.w;
        op[j] = o4;
        oh[2 * j]     = __floats2half2_rn(o4.x, o4.y);
        oh[2 * j + 1] = __floats2half2_rn(o4.z, o4.w);
    }
}

// ---------------------------------------------------------------------------
// Host driver
// ---------------------------------------------------------------------------
extern "C" void kernel_launch(void* const* d_in, const int* in_sizes, int n_in,
                              void* d_out, int out_size)
{
    const float* x   = (const float*)d_in[0];
    const float* wq  = (const float*)d_in[1];
    const float* bq  = (const float*)d_in[2];
    const float* wk  = (const float*)d_in[3];
    const float* bk  = (const float*)d_in[4];
    const float* wv  = (const float*)d_in[5];
    const float* bv  = (const float*)d_in[6];
    const float* wo  = (const float*)d_in[7];
    const float* bo  = (const float*)d_in[8];
    const float* g1  = (const float*)d_in[9];
    const float* be1 = (const float*)d_in[10];
    const float* w1  = (const float*)d_in[11];
    const float* b1  = (const float*)d_in[12];
    const float* w2  = (const float*)d_in[13];
    const float* b2  = (const float*)d_in[14];
    const float* g2  = (const float*)d_in[15];
    const float* be2 = (const float*)d_in[16];

    float *gx, *gtmp;
    __half *gxh, *gqkv, *gattn, *gffn, *gwH;
    cudaGetSymbolAddress((void**)&gx,    g_x);
    cudaGetSymbolAddress((void**)&gxh,   g_xh);
    cudaGetSymbolAddress((void**)&gqkv,  g_qkv);
    cudaGetSymbolAddress((void**)&gattn, g_attn);
    cudaGetSymbolAddress((void**)&gtmp,  g_tmp);
    cudaGetSymbolAddress((void**)&gffn,  g_ffn);
    cudaGetSymbolAddress((void**)&gwH,   g_wH);

    constexpr int SM_BIG = smem_bytes<128, 128>();   // 110592
    constexpr int SM_SML = smem_bytes<128, 64>();    // 82944
    (void)cudaFuncSetAttribute(mma_gemm<128,128,M_QKV>,  cudaFuncAttributeMaxDynamicSharedMemorySize, SM_BIG);
    (void)cudaFuncSetAttribute(mma_gemm<128,64,M_RES>,   cudaFuncAttributeMaxDynamicSharedMemorySize, SM_SML);
    (void)cudaFuncSetAttribute(mma_gemm<128,128,M_GELU>, cudaFuncAttributeMaxDynamicSharedMemorySize, SM_BIG);
    (void)cudaFuncSetAttribute(flash_k, cudaFuncAttributeMaxDynamicSharedMemorySize, FA_SMEM);

    copy_half<<<512, 256>>>(x, gx, gxh, M_ROWS * D_ / 4);
    prep_all<<<24576, dim3(32, 8)>>>(wq, wk, wv, wo, w1, w2, gwH);

    const __half* gq  = gqkv;
    const __half* gk  = gqkv + MD;
    const __half* gvT = gqkv + 2 * MD;

    const dim3 gQKV(1536 / 128, M_ROWS / 128);   // (12, 32)
    const dim3 gOP(512 / 64, M_ROWS / 128);      // (8, 32) = 256 CTAs
    const dim3 gF1(2048 / 128, M_ROWS / 128);    // (16, 32)
    const dim3 gFA(S_ / 128, B_ * H_);           // (8, 32)

    for (int l = 0; l < L_; l++) {
        const __half* wqkvH_l = gwH + OFF_TQKV + (long)l * SZ_QKV;
        const __half* woH_l   = gwH + OFF_TO   + (long)l * SZ_O;
        const __half* w1H_l   = gwH + OFF_T1   + (long)l * SZ_1;
        const __half* w2H_l   = gwH + OFF_T2   + (long)l * SZ_2;
        const float* bq_l = bq + (long)l * D_;
        const float* bk_l = bk + (long)l * D_;
        const float* bv_l = bv + (long)l * D_;
        const float* bo_l = bo + (long)l * D_;
        const float* b1_l = b1 + (long)l * F_;
        const float* b2_l = b2 + (long)l * D_;
        const float* g1_l = g1 + (long)l * D_;
        const float* g2_l = g2 + (long)l * D_;
        const float* be1_l = be1 + (long)l * D_;
        const float* be2_l = be2 + (long)l * D_;

        // fused QKV projection -> q,k [B,H,S,DH], vT [B,H,DH,S] (half)
        mma_gemm<128,128,M_QKV><<<gQKV, 256, SM_BIG>>>(
            gxh, wqkvH_l, bq_l, bk_l, bv_l, nullptr, nullptr, gqkv, 1536, 512);

        // fused attention (register-resident P)
        flash_k<<<gFA, 256, FA_SMEM>>>(gq, gk, gvT, gattn);

        // O projection + bias + residual (fp32 out), BN=64 for full-wave fill
        mma_gemm<128,64,M_RES><<<gOP, 256, SM_SML>>>(
            gattn, woH_l, bo_l, nullptr, nullptr, gx, gtmp, nullptr, 512, 512);
        ln_k<<<M_ROWS / 8, 256>>>(gtmp, g1_l, be1_l, gx, gxh);

        // FFN1 + GELU (half out)
        mma_gemm<128,128,M_GELU><<<gF1, 256, SM_BIG>>>(
            gxh, w1H_l, b1_l, nullptr, nullptr, nullptr, nullptr, gffn, 2048, 512);
        // FFN2 + bias + residual (fp32 out), BN=64
        mma_gemm<128,64,M_RES><<<gOP, 256, SM_SML>>>(
            gffn, w2H_l, b2_l, nullptr, nullptr, gx, gtmp, nullptr, 512, 2048);
        ln_k<<<M_ROWS / 8, 256>>>(gtmp, g2_l, be2_l,
                                  (l == L_ - 1) ? (float*)d_out : gx, gxh);
    }
}